// round 1
// baseline (speedup 1.0000x reference)
#include <cuda_runtime.h>
#include <math.h>

#define BB 256
#define NN 196
#define CC 784
#define HH 4
#define DD 196
#define MM (BB*NN)          // 50176 tokens

// ---------------- scratch (device globals: allocation-free rule) ------------
__device__ __align__(16) float g_Q[(size_t)MM * CC];          // 157 MB
__device__ __align__(16) float g_K[(size_t)MM * CC];
__device__ __align__(16) float g_V[(size_t)MM * CC];
__device__ __align__(16) float g_L[(size_t)BB * HH * NN * NN]; // logits / attn
__device__ __align__(16) float g_O[(size_t)MM * CC];           // attn output (B,N,C)
__device__ __align__(16) float g_CP[HH * NN * DD];             // rpe table

// ---------------- cp[h][p][k] = rel_h[h,k,p/14] + rel_w[h,k,p%14] ----------
__global__ void cp_kernel(const float* __restrict__ rel_h,
                          const float* __restrict__ rel_w) {
    int idx = blockIdx.x * blockDim.x + threadIdx.x;
    if (idx >= HH * NN * DD) return;
    int h   = idx / (NN * DD);
    int rem = idx - h * (NN * DD);
    int p   = rem / DD;
    int k   = rem - p * DD;
    g_CP[idx] = rel_h[(h * DD + k) * 14 + (p / 14)]
              + rel_w[(h * DD + k) * 14 + (p % 14)];
}

// ---------------- projection GEMM: Y[M,784] = X[M,784] @ W[784,784]^T + b ---
// BM=128, BN=112, BK=16; 256 threads, 8x7 per thread. All dims divide exactly.
__global__ __launch_bounds__(256) void proj_kernel(
    const float* __restrict__ X, const float* __restrict__ W,
    const float* __restrict__ bias, float* __restrict__ Y)
{
    __shared__ float As[16][128];
    __shared__ float Bs[16][112];
    const int t  = threadIdx.x;
    const int m0 = blockIdx.y * 128;
    const int n0 = blockIdx.x * 112;
    const int tx = t & 15;      // 0..15 -> 7 output cols each
    const int ty = t >> 4;      // 0..15 -> 8 output rows each

    float acc[8][7];
#pragma unroll
    for (int i = 0; i < 8; i++)
#pragma unroll
        for (int j = 0; j < 7; j++) acc[i][j] = 0.f;

    for (int k0 = 0; k0 < CC; k0 += 16) {
        // A tile: 128 rows x 16 cols = 512 float4
        for (int v = t; v < 512; v += 256) {
            int r = v >> 2, c4 = (v & 3) * 4;
            float4 f = *(const float4*)(X + (size_t)(m0 + r) * CC + k0 + c4);
            As[c4 + 0][r] = f.x; As[c4 + 1][r] = f.y;
            As[c4 + 2][r] = f.z; As[c4 + 3][r] = f.w;
        }
        // B tile: 112 rows x 16 cols = 448 float4
        for (int v = t; v < 448; v += 256) {
            int r = v >> 2, c4 = (v & 3) * 4;
            float4 f = *(const float4*)(W + (size_t)(n0 + r) * CC + k0 + c4);
            Bs[c4 + 0][r] = f.x; Bs[c4 + 1][r] = f.y;
            Bs[c4 + 2][r] = f.z; Bs[c4 + 3][r] = f.w;
        }
        __syncthreads();
#pragma unroll
        for (int kk = 0; kk < 16; kk++) {
            float a[8], bb[7];
#pragma unroll
            for (int i = 0; i < 8; i++) a[i] = As[kk][ty * 8 + i];
#pragma unroll
            for (int j = 0; j < 7; j++) bb[j] = Bs[kk][tx * 7 + j];
#pragma unroll
            for (int i = 0; i < 8; i++)
#pragma unroll
                for (int j = 0; j < 7; j++)
                    acc[i][j] = fmaf(a[i], bb[j], acc[i][j]);
        }
        __syncthreads();
    }
#pragma unroll
    for (int j = 0; j < 7; j++) {
        float bj = bias[n0 + tx * 7 + j];
#pragma unroll
        for (int i = 0; i < 8; i++)
            Y[(size_t)(m0 + ty * 8 + i) * CC + n0 + tx * 7 + j] = acc[i][j] + bj;
    }
}

// ---------------- logits: L[bh][n][m] = (Q@K^T)/14 + cp@Q -------------------
// per (b,h): 196x196 out, 98x98 tiles (2x2 grid), 196 thr, 7x7 per thread.
__global__ __launch_bounds__(196) void attn_logits_kernel()
{
    __shared__ float As[14][98];
    __shared__ float Bs[14][98];
    const int t  = threadIdx.x;
    const int bh = blockIdx.z;
    const int b  = bh / HH, h = bh % HH;
    const int n0 = blockIdx.y * 98;
    const int m0 = blockIdx.x * 98;
    const int tx = t % 14, ty = t / 14;

    const float* Qb = g_Q + (size_t)b * NN * CC + h * DD;
    const float* Kb = g_K + (size_t)b * NN * CC + h * DD;

    float acc[7][7];
#pragma unroll
    for (int i = 0; i < 7; i++)
#pragma unroll
        for (int j = 0; j < 7; j++) acc[i][j] = 0.f;

    // pass 1: sim = Q @ K^T (contract over d)
    for (int k0 = 0; k0 < DD; k0 += 14) {
        for (int v = t; v < 1372; v += 196) {
            int r = v / 14, c = v - r * 14;
            As[c][r] = Qb[(size_t)(n0 + r) * CC + k0 + c];
            Bs[c][r] = Kb[(size_t)(m0 + r) * CC + k0 + c];
        }
        __syncthreads();
#pragma unroll
        for (int kk = 0; kk < 14; kk++) {
            float a[7], bb[7];
#pragma unroll
            for (int i = 0; i < 7; i++) a[i]  = As[kk][ty * 7 + i];
#pragma unroll
            for (int j = 0; j < 7; j++) bb[j] = Bs[kk][tx * 7 + j];
#pragma unroll
            for (int i = 0; i < 7; i++)
#pragma unroll
                for (int j = 0; j < 7; j++)
                    acc[i][j] = fmaf(a[i], bb[j], acc[i][j]);
        }
        __syncthreads();
    }
#pragma unroll
    for (int i = 0; i < 7; i++)
#pragma unroll
        for (int j = 0; j < 7; j++) acc[i][j] *= (1.0f / 14.0f);

    // pass 2: pos = cp @ Q (contract over q's TOKEN axis — faithful to ref)
    const float* cpb = g_CP + h * NN * DD;
    for (int k0 = 0; k0 < NN; k0 += 14) {
        for (int v = t; v < 1372; v += 196) {
            int r = v / 14, c = v - r * 14;
            As[c][r] = cpb[(n0 + r) * DD + k0 + c];
        }
        for (int v = t; v < 1372; v += 196) {
            int kr = v / 98, mc = v - kr * 98;
            Bs[kr][mc] = Qb[(size_t)(k0 + kr) * CC + m0 + mc];
        }
        __syncthreads();
#pragma unroll
        for (int kk = 0; kk < 14; kk++) {
            float a[7], bb[7];
#pragma unroll
            for (int i = 0; i < 7; i++) a[i]  = As[kk][ty * 7 + i];
#pragma unroll
            for (int j = 0; j < 7; j++) bb[j] = Bs[kk][tx * 7 + j];
#pragma unroll
            for (int i = 0; i < 7; i++)
#pragma unroll
                for (int j = 0; j < 7; j++)
                    acc[i][j] = fmaf(a[i], bb[j], acc[i][j]);
        }
        __syncthreads();
    }

    float* Lb = g_L + (size_t)bh * NN * NN;
#pragma unroll
    for (int i = 0; i < 7; i++)
#pragma unroll
        for (int j = 0; j < 7; j++)
            Lb[(size_t)(n0 + ty * 7 + i) * NN + m0 + tx * 7 + j] = acc[i][j];
}

// ---------------- softmax: one warp per 196-wide row ------------------------
__global__ __launch_bounds__(256) void softmax_kernel()
{
    const int warp = threadIdx.x >> 5, lane = threadIdx.x & 31;
    const size_t row = (size_t)blockIdx.x * 8 + warp;   // 200704 rows total
    float* p = g_L + row * NN;

    float v[7];
    float mx = -1e30f;
#pragma unroll
    for (int s = 0; s < 7; s++) {
        int idx = lane + s * 32;
        v[s] = (idx < NN) ? p[idx] : -1e30f;
        mx = fmaxf(mx, v[s]);
    }
#pragma unroll
    for (int o = 16; o; o >>= 1) mx = fmaxf(mx, __shfl_xor_sync(0xffffffffu, mx, o));
    float sum = 0.f;
#pragma unroll
    for (int s = 0; s < 7; s++) { v[s] = __expf(v[s] - mx); sum += v[s]; }
#pragma unroll
    for (int o = 16; o; o >>= 1) sum += __shfl_xor_sync(0xffffffffu, sum, o);
    float inv = 1.0f / sum;
#pragma unroll
    for (int s = 0; s < 7; s++) {
        int idx = lane + s * 32;
        if (idx < NN) p[idx] = v[s] * inv;
    }
}

// ---------------- out = attn @ V, stored transposed into (B,N,C) ------------
__global__ __launch_bounds__(196) void attn_v_kernel()
{
    __shared__ float As[14][98];
    __shared__ float Bs[14][98];
    const int t  = threadIdx.x;
    const int bh = blockIdx.z;
    const int b  = bh / HH, h = bh % HH;
    const int n0 = blockIdx.y * 98;
    const int c0 = blockIdx.x * 98;
    const int tx = t % 14, ty = t / 14;

    const float* Lb = g_L + (size_t)bh * NN * NN;
    const float* Vb = g_V + (size_t)b * NN * CC + h * DD;

    float acc[7][7];
#pragma unroll
    for (int i = 0; i < 7; i++)
#pragma unroll
        for (int j = 0; j < 7; j++) acc[i][j] = 0.f;

    for (int m0 = 0; m0 < NN; m0 += 14) {
        for (int v = t; v < 1372; v += 196) {
            int r = v / 14, c = v - r * 14;
            As[c][r] = Lb[(size_t)(n0 + r) * NN + m0 + c];
        }
        for (int v = t; v < 1372; v += 196) {
            int kr = v / 98, mc = v - kr * 98;
            Bs[kr][mc] = Vb[(size_t)(m0 + kr) * CC + c0 + mc];
        }
        __syncthreads();
#pragma unroll
        for (int kk = 0; kk < 14; kk++) {
            float a[7], bb[7];
#pragma unroll
            for (int i = 0; i < 7; i++) a[i]  = As[kk][ty * 7 + i];
#pragma unroll
            for (int j = 0; j < 7; j++) bb[j] = Bs[kk][tx * 7 + j];
#pragma unroll
            for (int i = 0; i < 7; i++)
#pragma unroll
                for (int j = 0; j < 7; j++)
                    acc[i][j] = fmaf(a[i], bb[j], acc[i][j]);
        }
        __syncthreads();
    }

    float* Ob = g_O + (size_t)b * NN * CC + h * DD;
#pragma unroll
    for (int i = 0; i < 7; i++)
#pragma unroll
        for (int j = 0; j < 7; j++)
            Ob[(size_t)(n0 + ty * 7 + i) * CC + c0 + tx * 7 + j] = acc[i][j];
}

// ---------------- launcher --------------------------------------------------
extern "C" void kernel_launch(void* const* d_in, const int* in_sizes, int n_in,
                              void* d_out, int out_size)
{
    const float* x     = (const float*)d_in[0];
    const float* Wq    = (const float*)d_in[1];
    const float* bq    = (const float*)d_in[2];
    const float* Wk    = (const float*)d_in[3];
    const float* bk    = (const float*)d_in[4];
    const float* Wv    = (const float*)d_in[5];
    const float* bv    = (const float*)d_in[6];
    const float* Wo    = (const float*)d_in[7];
    const float* bo    = (const float*)d_in[8];
    const float* rel_h = (const float*)d_in[9];
    const float* rel_w = (const float*)d_in[10];
    float* out = (float*)d_out;

    float *pQ, *pK, *pV, *pO;
    cudaGetSymbolAddress((void**)&pQ, g_Q);
    cudaGetSymbolAddress((void**)&pK, g_K);
    cudaGetSymbolAddress((void**)&pV, g_V);
    cudaGetSymbolAddress((void**)&pO, g_O);

    cp_kernel<<<(HH * NN * DD + 255) / 256, 256>>>(rel_h, rel_w);

    dim3 pgrid(CC / 112, MM / 128);   // (7, 392)
    proj_kernel<<<pgrid, 256>>>(x, Wq, bq, pQ);
    proj_kernel<<<pgrid, 256>>>(x, Wk, bk, pK);
    proj_kernel<<<pgrid, 256>>>(x, Wv, bv, pV);

    attn_logits_kernel<<<dim3(2, 2, BB * HH), 196>>>();
    softmax_kernel<<<BB * HH * NN / 8, 256>>>();
    attn_v_kernel<<<dim3(2, 2, BB * HH), 196>>>();

    proj_kernel<<<pgrid, 256>>>(pO, Wo, bo, out);
}

// round 3
// speedup vs baseline: 1.8492x; 1.8492x over previous
#include <cuda_runtime.h>
#include <cuda_fp16.h>
#include <math.h>

#define BB 256
#define NN 196
#define CC 784
#define HH 4
#define DD 196
#define MM (BB*NN)          // 50176 tokens

// ---------------- scratch (device globals: allocation-free rule) ------------
__device__ __align__(16) float  g_Q[(size_t)MM * CC];           // 157 MB
__device__ __align__(16) float  g_K[(size_t)MM * CC];
__device__ __align__(16) float  g_V[(size_t)MM * CC];
__device__ __align__(16) float  g_L[(size_t)BB * HH * NN * NN]; // logits / attn
__device__ __align__(16) float  g_CP[HH * NN * DD];             // rpe table
__device__ __align__(16) __half g_Xh[(size_t)MM * CC];          // x hi
__device__ __align__(16) __half g_Xl[(size_t)MM * CC];          // x lo
__device__ __align__(16) __half g_Oh[(size_t)MM * CC];          // attn out hi
__device__ __align__(16) __half g_Ol[(size_t)MM * CC];          // attn out lo
__device__ __align__(16) __half g_Wh[4][CC * CC];               // weights hi (q,k,v,o)
__device__ __align__(16) __half g_Wl[4][CC * CC];               // weights lo

// ---------------- f32 -> (f16 hi, f16 lo) split -----------------------------
__global__ void f2h_split_kernel(const float* __restrict__ in,
                                 __half* __restrict__ hi,
                                 __half* __restrict__ lo, int n) {
    int i = blockIdx.x * blockDim.x + threadIdx.x;
    if (i >= n) return;
    float f = in[i];
    __half h = __float2half_rn(f);
    hi[i] = h;
    lo[i] = __float2half_rn(f - __half2float(h));
}

// ---------------- cp[h][p][k] = rel_h[h,k,p/14] + rel_w[h,k,p%14] ----------
__global__ void cp_kernel(const float* __restrict__ rel_h,
                          const float* __restrict__ rel_w) {
    int idx = blockIdx.x * blockDim.x + threadIdx.x;
    if (idx >= HH * NN * DD) return;
    int h   = idx / (NN * DD);
    int rem = idx - h * (NN * DD);
    int p   = rem / DD;
    int k   = rem - p * DD;
    g_CP[idx] = rel_h[(h * DD + k) * 14 + (p / 14)]
              + rel_w[(h * DD + k) * 14 + (p % 14)];
}

// ---------------- split-fp16 HMMA projection GEMM ---------------------------
// Y = (Ahi+Alo)[M,784] @ (Whi+Wlo)[784,784]^T + bias, 3-term Markidis.
// BM=128, BN=112, BK=112, 8 warps (4m x 2n), warp tile 32x56 (2x7 m16n8k16).
#define ASTRIDE 120   // halves per smem row (240B: conflict-free ldmatrix)

__global__ __launch_bounds__(256) void hgemm_proj3(
    const __half* __restrict__ Ah, const __half* __restrict__ Al,
    const __half* __restrict__ Wh, const __half* __restrict__ Wl,
    const float* __restrict__ bias, float* __restrict__ Y)
{
    extern __shared__ __half sm[];
    __half* Ash = sm;                          // [128][120]
    __half* Asl = sm + 128 * ASTRIDE;
    __half* Bsh = sm + 2 * 128 * ASTRIDE;      // [112][120]
    __half* Bsl = sm + 2 * 128 * ASTRIDE + 112 * ASTRIDE;

    const int t    = threadIdx.x;
    const int lane = t & 31;
    const int wid  = t >> 5;
    const int wm   = wid & 3;           // 0..3
    const int wn   = wid >> 2;          // 0..1
    const int m0   = blockIdx.y * 128;
    const int n0   = blockIdx.x * 112;

    float acc[2][7][4];
#pragma unroll
    for (int i = 0; i < 2; i++)
#pragma unroll
        for (int j = 0; j < 7; j++)
#pragma unroll
            for (int r = 0; r < 4; r++) acc[i][j][r] = 0.f;

    for (int k0 = 0; k0 < CC; k0 += 112) {
        // A tiles: 128 rows x 112 halves = 1792 uint4 each (hi, lo)
        for (int v = t; v < 1792; v += 256) {
            int r = v / 14, c = v - r * 14;
            size_t goff = (size_t)(m0 + r) * CC + k0 + c * 8;
            *(uint4*)(Ash + r * ASTRIDE + c * 8) = *(const uint4*)(Ah + goff);
            *(uint4*)(Asl + r * ASTRIDE + c * 8) = *(const uint4*)(Al + goff);
        }
        // B tiles: 112 rows x 112 halves = 1568 uint4 each
        for (int v = t; v < 1568; v += 256) {
            int r = v / 14, c = v - r * 14;
            size_t goff = (size_t)(n0 + r) * CC + k0 + c * 8;
            *(uint4*)(Bsh + r * ASTRIDE + c * 8) = *(const uint4*)(Wh + goff);
            *(uint4*)(Bsl + r * ASTRIDE + c * 8) = *(const uint4*)(Wl + goff);
        }
        __syncthreads();

#pragma unroll
        for (int kk = 0; kk < 7; kk++) {
            const int kOff = kk * 16;
            // A fragments (hi, lo): 2 m16 tiles each, ldmatrix.x4 non-trans
            unsigned afh[2][4], afl[2][4];
#pragma unroll
            for (int mt = 0; mt < 2; mt++) {
                int arow = wm * 32 + mt * 16 + (lane & 15);
                int acol = kOff + ((lane >> 4) << 3);
                unsigned sa = (unsigned)__cvta_generic_to_shared(Ash + arow * ASTRIDE + acol);
                asm volatile("ldmatrix.sync.aligned.m8n8.x4.shared.b16 {%0,%1,%2,%3}, [%4];"
                             : "=r"(afh[mt][0]), "=r"(afh[mt][1]), "=r"(afh[mt][2]), "=r"(afh[mt][3])
                             : "r"(sa));
                unsigned sal = (unsigned)__cvta_generic_to_shared(Asl + arow * ASTRIDE + acol);
                asm volatile("ldmatrix.sync.aligned.m8n8.x4.shared.b16 {%0,%1,%2,%3}, [%4];"
                             : "=r"(afl[mt][0]), "=r"(afl[mt][1]), "=r"(afl[mt][2]), "=r"(afl[mt][3])
                             : "r"(sal));
            }
            // B fragments (hi, lo): 7 n8 tiles; 3 x4 (pairs) + 1 x2
            unsigned bfh[7][2], bfl[7][2];
#pragma unroll
            for (int p = 0; p < 3; p++) {
                int brow = wn * 56 + p * 16 + (lane & 7) + ((lane & 16) >> 1);
                int bcol = kOff + (lane & 8);
                unsigned sb = (unsigned)__cvta_generic_to_shared(Bsh + brow * ASTRIDE + bcol);
                asm volatile("ldmatrix.sync.aligned.m8n8.x4.shared.b16 {%0,%1,%2,%3}, [%4];"
                             : "=r"(bfh[2*p][0]), "=r"(bfh[2*p][1]), "=r"(bfh[2*p+1][0]), "=r"(bfh[2*p+1][1])
                             : "r"(sb));
                unsigned sbl = (unsigned)__cvta_generic_to_shared(Bsl + brow * ASTRIDE + bcol);
                asm volatile("ldmatrix.sync.aligned.m8n8.x4.shared.b16 {%0,%1,%2,%3}, [%4];"
                             : "=r"(bfl[2*p][0]), "=r"(bfl[2*p][1]), "=r"(bfl[2*p+1][0]), "=r"(bfl[2*p+1][1])
                             : "r"(sbl));
            }
            {
                int brow = wn * 56 + 48 + (lane & 7);
                int bcol = kOff + (lane & 8);
                unsigned sb = (unsigned)__cvta_generic_to_shared(Bsh + brow * ASTRIDE + bcol);
                asm volatile("ldmatrix.sync.aligned.m8n8.x2.shared.b16 {%0,%1}, [%2];"
                             : "=r"(bfh[6][0]), "=r"(bfh[6][1])
                             : "r"(sb));
                unsigned sbl = (unsigned)__cvta_generic_to_shared(Bsl + brow * ASTRIDE + bcol);
                asm volatile("ldmatrix.sync.aligned.m8n8.x2.shared.b16 {%0,%1}, [%2];"
                             : "=r"(bfl[6][0]), "=r"(bfl[6][1])
                             : "r"(sbl));
            }
#pragma unroll
            for (int mt = 0; mt < 2; mt++)
#pragma unroll
                for (int nt = 0; nt < 7; nt++) {
                    // hi*hi
                    asm volatile(
                        "mma.sync.aligned.m16n8k16.row.col.f32.f16.f16.f32 "
                        "{%0,%1,%2,%3}, {%4,%5,%6,%7}, {%8,%9}, {%0,%1,%2,%3};"
                        : "+f"(acc[mt][nt][0]), "+f"(acc[mt][nt][1]),
                          "+f"(acc[mt][nt][2]), "+f"(acc[mt][nt][3])
                        : "r"(afh[mt][0]), "r"(afh[mt][1]), "r"(afh[mt][2]), "r"(afh[mt][3]),
                          "r"(bfh[nt][0]), "r"(bfh[nt][1]));
                    // hi*lo
                    asm volatile(
                        "mma.sync.aligned.m16n8k16.row.col.f32.f16.f16.f32 "
                        "{%0,%1,%2,%3}, {%4,%5,%6,%7}, {%8,%9}, {%0,%1,%2,%3};"
                        : "+f"(acc[mt][nt][0]), "+f"(acc[mt][nt][1]),
                          "+f"(acc[mt][nt][2]), "+f"(acc[mt][nt][3])
                        : "r"(afh[mt][0]), "r"(afh[mt][1]), "r"(afh[mt][2]), "r"(afh[mt][3]),
                          "r"(bfl[nt][0]), "r"(bfl[nt][1]));
                    // lo*hi
                    asm volatile(
                        "mma.sync.aligned.m16n8k16.row.col.f32.f16.f16.f32 "
                        "{%0,%1,%2,%3}, {%4,%5,%6,%7}, {%8,%9}, {%0,%1,%2,%3};"
                        : "+f"(acc[mt][nt][0]), "+f"(acc[mt][nt][1]),
                          "+f"(acc[mt][nt][2]), "+f"(acc[mt][nt][3])
                        : "r"(afl[mt][0]), "r"(afl[mt][1]), "r"(afl[mt][2]), "r"(afl[mt][3]),
                          "r"(bfh[nt][0]), "r"(bfh[nt][1]));
                }
        }
        __syncthreads();
    }

    // epilogue: C frag lane mapping m16n8: row = l/4 (+8), col = (l%4)*2 (+1)
#pragma unroll
    for (int mt = 0; mt < 2; mt++) {
#pragma unroll
        for (int nt = 0; nt < 7; nt++) {
            int row = m0 + wm * 32 + mt * 16 + (lane >> 2);
            int col = n0 + wn * 56 + nt * 8 + (lane & 3) * 2;
            float b0 = bias[col], b1 = bias[col + 1];
            float2 v0 = make_float2(acc[mt][nt][0] + b0, acc[mt][nt][1] + b1);
            float2 v1 = make_float2(acc[mt][nt][2] + b0, acc[mt][nt][3] + b1);
            *(float2*)(Y + (size_t)row * CC + col) = v0;
            *(float2*)(Y + (size_t)(row + 8) * CC + col) = v1;
        }
    }
}

// ---------------- logits: L[bh][n][m] = (Q@K^T)/14 + cp@Q (fp32 SIMT) ------
__global__ __launch_bounds__(196) void attn_logits_kernel()
{
    __shared__ float As[14][98];
    __shared__ float Bs[14][98];
    const int t  = threadIdx.x;
    const int bh = blockIdx.z;
    const int b  = bh / HH, h = bh % HH;
    const int n0 = blockIdx.y * 98;
    const int m0 = blockIdx.x * 98;
    const int tx = t % 14, ty = t / 14;

    const float* Qb = g_Q + (size_t)b * NN * CC + h * DD;
    const float* Kb = g_K + (size_t)b * NN * CC + h * DD;

    float acc[7][7];
#pragma unroll
    for (int i = 0; i < 7; i++)
#pragma unroll
        for (int j = 0; j < 7; j++) acc[i][j] = 0.f;

    for (int k0 = 0; k0 < DD; k0 += 14) {
        for (int v = t; v < 1372; v += 196) {
            int r = v / 14, c = v - r * 14;
            As[c][r] = Qb[(size_t)(n0 + r) * CC + k0 + c];
            Bs[c][r] = Kb[(size_t)(m0 + r) * CC + k0 + c];
        }
        __syncthreads();
#pragma unroll
        for (int kk = 0; kk < 14; kk++) {
            float a[7], bb[7];
#pragma unroll
            for (int i = 0; i < 7; i++) a[i]  = As[kk][ty * 7 + i];
#pragma unroll
            for (int j = 0; j < 7; j++) bb[j] = Bs[kk][tx * 7 + j];
#pragma unroll
            for (int i = 0; i < 7; i++)
#pragma unroll
                for (int j = 0; j < 7; j++)
                    acc[i][j] = fmaf(a[i], bb[j], acc[i][j]);
        }
        __syncthreads();
    }
#pragma unroll
    for (int i = 0; i < 7; i++)
#pragma unroll
        for (int j = 0; j < 7; j++) acc[i][j] *= (1.0f / 14.0f);

    const float* cpb = g_CP + h * NN * DD;
    for (int k0 = 0; k0 < NN; k0 += 14) {
        for (int v = t; v < 1372; v += 196) {
            int r = v / 14, c = v - r * 14;
            As[c][r] = cpb[(n0 + r) * DD + k0 + c];
        }
        for (int v = t; v < 1372; v += 196) {
            int kr = v / 98, mc = v - kr * 98;
            Bs[kr][mc] = Qb[(size_t)(k0 + kr) * CC + m0 + mc];
        }
        __syncthreads();
#pragma unroll
        for (int kk = 0; kk < 14; kk++) {
            float a[7], bb[7];
#pragma unroll
            for (int i = 0; i < 7; i++) a[i]  = As[kk][ty * 7 + i];
#pragma unroll
            for (int j = 0; j < 7; j++) bb[j] = Bs[kk][tx * 7 + j];
#pragma unroll
            for (int i = 0; i < 7; i++)
#pragma unroll
                for (int j = 0; j < 7; j++)
                    acc[i][j] = fmaf(a[i], bb[j], acc[i][j]);
        }
        __syncthreads();
    }

    float* Lb = g_L + (size_t)bh * NN * NN;
#pragma unroll
    for (int i = 0; i < 7; i++)
#pragma unroll
        for (int j = 0; j < 7; j++)
            Lb[(size_t)(n0 + ty * 7 + i) * NN + m0 + tx * 7 + j] = acc[i][j];
}

// ---------------- softmax: one warp per 196-wide row ------------------------
__global__ __launch_bounds__(256) void softmax_kernel()
{
    const int warp = threadIdx.x >> 5, lane = threadIdx.x & 31;
    const size_t row = (size_t)blockIdx.x * 8 + warp;
    float* p = g_L + row * NN;

    float v[7];
    float mx = -1e30f;
#pragma unroll
    for (int s = 0; s < 7; s++) {
        int idx = lane + s * 32;
        v[s] = (idx < NN) ? p[idx] : -1e30f;
        mx = fmaxf(mx, v[s]);
    }
#pragma unroll
    for (int o = 16; o; o >>= 1) mx = fmaxf(mx, __shfl_xor_sync(0xffffffffu, mx, o));
    float sum = 0.f;
#pragma unroll
    for (int s = 0; s < 7; s++) { v[s] = __expf(v[s] - mx); sum += v[s]; }
#pragma unroll
    for (int o = 16; o; o >>= 1) sum += __shfl_xor_sync(0xffffffffu, sum, o);
    float inv = 1.0f / sum;
#pragma unroll
    for (int s = 0; s < 7; s++) {
        int idx = lane + s * 32;
        if (idx < NN) p[idx] = v[s] * inv;
    }
}

// ---------------- out = attn @ V, stored hi/lo fp16 into (B,N,C) ------------
__global__ __launch_bounds__(196) void attn_v_kernel()
{
    __shared__ float As[14][98];
    __shared__ float Bs[14][98];
    const int t  = threadIdx.x;
    const int bh = blockIdx.z;
    const int b  = bh / HH, h = bh % HH;
    const int n0 = blockIdx.y * 98;
    const int c0 = blockIdx.x * 98;
    const int tx = t % 14, ty = t / 14;

    const float* Lb = g_L + (size_t)bh * NN * NN;
    const float* Vb = g_V + (size_t)b * NN * CC + h * DD;

    float acc[7][7];
#pragma unroll
    for (int i = 0; i < 7; i++)
#pragma unroll
        for (int j = 0; j < 7; j++) acc[i][j] = 0.f;

    for (int m0 = 0; m0 < NN; m0 += 14) {
        for (int v = t; v < 1372; v += 196) {
            int r = v / 14, c = v - r * 14;
            As[c][r] = Lb[(size_t)(n0 + r) * NN + m0 + c];
        }
        for (int v = t; v < 1372; v += 196) {
            int kr = v / 98, mc = v - kr * 98;
            Bs[kr][mc] = Vb[(size_t)(m0 + kr) * CC + c0 + mc];
        }
        __syncthreads();
#pragma unroll
        for (int kk = 0; kk < 14; kk++) {
            float a[7], bb[7];
#pragma unroll
            for (int i = 0; i < 7; i++) a[i]  = As[kk][ty * 7 + i];
#pragma unroll
            for (int j = 0; j < 7; j++) bb[j] = Bs[kk][tx * 7 + j];
#pragma unroll
            for (int i = 0; i < 7; i++)
#pragma unroll
                for (int j = 0; j < 7; j++)
                    acc[i][j] = fmaf(a[i], bb[j], acc[i][j]);
        }
        __syncthreads();
    }

    __half* Oh = g_Oh + (size_t)b * NN * CC + h * DD;
    __half* Ol = g_Ol + (size_t)b * NN * CC + h * DD;
#pragma unroll
    for (int i = 0; i < 7; i++)
#pragma unroll
        for (int j = 0; j < 7; j++) {
            float  f = acc[i][j];
            __half h2 = __float2half_rn(f);
            size_t off = (size_t)(n0 + ty * 7 + i) * CC + c0 + tx * 7 + j;
            Oh[off] = h2;
            Ol[off] = __float2half_rn(f - __half2float(h2));
        }
}

// ---------------- launcher --------------------------------------------------
extern "C" void kernel_launch(void* const* d_in, const int* in_sizes, int n_in,
                              void* d_out, int out_size)
{
    const float* x     = (const float*)d_in[0];
    const float* Wq    = (const float*)d_in[1];
    const float* bq    = (const float*)d_in[2];
    const float* Wk    = (const float*)d_in[3];
    const float* bk    = (const float*)d_in[4];
    const float* Wv    = (const float*)d_in[5];
    const float* bv    = (const float*)d_in[6];
    const float* Wo    = (const float*)d_in[7];
    const float* bo    = (const float*)d_in[8];
    const float* rel_h = (const float*)d_in[9];
    const float* rel_w = (const float*)d_in[10];
    float* out = (float*)d_out;

    float  *pQ, *pK, *pV;
    __half *pXh, *pXl, *pOh, *pOl, *pWh, *pWl;
    cudaGetSymbolAddress((void**)&pQ,  g_Q);
    cudaGetSymbolAddress((void**)&pK,  g_K);
    cudaGetSymbolAddress((void**)&pV,  g_V);
    cudaGetSymbolAddress((void**)&pXh, g_Xh);
    cudaGetSymbolAddress((void**)&pXl, g_Xl);
    cudaGetSymbolAddress((void**)&pOh, g_Oh);
    cudaGetSymbolAddress((void**)&pOl, g_Ol);
    cudaGetSymbolAddress((void**)&pWh, g_Wh);
    cudaGetSymbolAddress((void**)&pWl, g_Wl);

    const unsigned smem = 2 * (128 + 112) * ASTRIDE * sizeof(__half); // 115200 B
    cudaFuncSetAttribute(hgemm_proj3,
        cudaFuncAttributeMaxDynamicSharedMemorySize, smem);

    // hi/lo splits
    const int xn = MM * CC;
    const int wn = CC * CC;
    f2h_split_kernel<<<(xn + 255) / 256, 256>>>(x,  pXh,          pXl,          xn);
    f2h_split_kernel<<<(wn + 255) / 256, 256>>>(Wq, pWh + 0 * wn, pWl + 0 * wn, wn);
    f2h_split_kernel<<<(wn + 255) / 256, 256>>>(Wk, pWh + 1 * wn, pWl + 1 * wn, wn);
    f2h_split_kernel<<<(wn + 255) / 256, 256>>>(Wv, pWh + 2 * wn, pWl + 2 * wn, wn);
    f2h_split_kernel<<<(wn + 255) / 256, 256>>>(Wo, pWh + 3 * wn, pWl + 3 * wn, wn);

    cp_kernel<<<(HH * NN * DD + 255) / 256, 256>>>(rel_h, rel_w);

    dim3 pgrid(CC / 112, MM / 128);   // (7, 392)
    hgemm_proj3<<<pgrid, 256, smem>>>(pXh, pXl, pWh + 0 * wn, pWl + 0 * wn, bq, pQ);
    hgemm_proj3<<<pgrid, 256, smem>>>(pXh, pXl, pWh + 1 * wn, pWl + 1 * wn, bk, pK);
    hgemm_proj3<<<pgrid, 256, smem>>>(pXh, pXl, pWh + 2 * wn, pWl + 2 * wn, bv, pV);

    attn_logits_kernel<<<dim3(2, 2, BB * HH), 196>>>();
    softmax_kernel<<<BB * HH * NN / 8, 256>>>();
    attn_v_kernel<<<dim3(2, 2, BB * HH), 196>>>();

    hgemm_proj3<<<pgrid, 256, smem>>>(pOh, pOl, pWh + 3 * wn, pWl + 3 * wn, bo, out);
}

// round 4
// speedup vs baseline: 1.9266x; 1.0419x over previous
#include <cuda_runtime.h>
#include <cuda_fp16.h>
#include <math.h>

#define BB 256
#define NN 196
#define CC 784
#define HH 4
#define DD 196
#define MM (BB*NN)          // 50176 tokens

// ---------------- scratch (device globals: allocation-free rule) ------------
__device__ __align__(16) float  g_Q[(size_t)MM * CC];           // 157 MB
__device__ __align__(16) float  g_K[(size_t)MM * CC];
__device__ __align__(16) float  g_V[(size_t)MM * CC];
__device__ __align__(16) float  g_L[(size_t)BB * HH * NN * NN]; // logits / attn
__device__ __align__(16) float  g_CP[HH * NN * DD];             // rpe table
__device__ __align__(16) __half g_Xh[(size_t)MM * CC];          // x hi
__device__ __align__(16) __half g_Xl[(size_t)MM * CC];          // x lo
__device__ __align__(16) __half g_Oh[(size_t)MM * CC];          // attn out hi
__device__ __align__(16) __half g_Ol[(size_t)MM * CC];          // attn out lo
__device__ __align__(16) __half g_Wh[4][CC * CC];               // weights hi (q,k,v,o)
__device__ __align__(16) __half g_Wl[4][CC * CC];               // weights lo

// ---------------- f32 -> (f16 hi, f16 lo) split -----------------------------
__global__ void f2h_split_kernel(const float* __restrict__ in,
                                 __half* __restrict__ hi,
                                 __half* __restrict__ lo, int n) {
    int i = blockIdx.x * blockDim.x + threadIdx.x;
    if (i >= n) return;
    float f = in[i];
    __half h = __float2half_rn(f);
    hi[i] = h;
    lo[i] = __float2half_rn(f - __half2float(h));
}

// ---------------- cp[h][p][k] = rel_h[h,k,p/14] + rel_w[h,k,p%14] ----------
__global__ void cp_kernel(const float* __restrict__ rel_h,
                          const float* __restrict__ rel_w) {
    int idx = blockIdx.x * blockDim.x + threadIdx.x;
    if (idx >= HH * NN * DD) return;
    int h   = idx / (NN * DD);
    int rem = idx - h * (NN * DD);
    int p   = rem / DD;
    int k   = rem - p * DD;
    g_CP[idx] = rel_h[(h * DD + k) * 14 + (p / 14)]
              + rel_w[(h * DD + k) * 14 + (p % 14)];
}

// ---------------- split-fp16 HMMA projection GEMM, cp.async 4-stage ---------
// Y = (Ahi+Alo)[M,784] @ (Whi+Wlo)[784,784]^T + bias, 3-term Markidis.
// BM=128, BN=112, BK=16, 8 warps (4m x 2n), warp tile 32x56 (2x7 m16n8k16).
#define AST2 24                      // halves per smem row (48B, conflict-free)
#define STAGE_HALVES ((128 + 128 + 112 + 112) * AST2)   // 11520 halves = 23040B
#define NSTAGE 4
#define KITERS 49                    // 784 / 16

__global__ __launch_bounds__(256) void hgemm_proj3(
    const __half* __restrict__ Ah, const __half* __restrict__ Al,
    const __half* __restrict__ Wh, const __half* __restrict__ Wl,
    const float* __restrict__ bias, float* __restrict__ Y)
{
    extern __shared__ __half sm[];

    const int t    = threadIdx.x;
    const int lane = t & 31;
    const int wid  = t >> 5;
    const int wm   = wid & 3;           // 0..3
    const int wn   = wid >> 2;          // 0..1
    const int m0   = blockIdx.y * 128;
    const int n0   = blockIdx.x * 112;

    float acc[2][7][4];
#pragma unroll
    for (int i = 0; i < 2; i++)
#pragma unroll
        for (int j = 0; j < 7; j++)
#pragma unroll
            for (int r = 0; r < 4; r++) acc[i][j][r] = 0.f;

    // ---- cp.async prefetch of one BK=16 stage ----
    auto prefetch = [&](int kt) {
        const int k0 = kt * 16;
        __half* st = sm + (kt & (NSTAGE - 1)) * STAGE_HALVES;
        // 960 16B copies: A-hi 256, A-lo 256, B-hi 224, B-lo 224
        for (int v = t; v < 960; v += 256) {
            const __half* g;
            __half* s;
            if (v < 512) {
                int part = v >> 8;          // 0 = hi, 1 = lo
                int rem  = v & 255;
                int row  = rem >> 1, ch = rem & 1;
                g = (part ? Al : Ah) + (size_t)(m0 + row) * CC + k0 + ch * 8;
                s = st + part * (128 * AST2) + row * AST2 + ch * 8;
            } else {
                int v2   = v - 512;
                int part = v2 / 224;
                int rem  = v2 % 224;
                int row  = rem >> 1, ch = rem & 1;
                g = (part ? Wl : Wh) + (size_t)(n0 + row) * CC + k0 + ch * 8;
                s = st + 256 * AST2 + part * (112 * AST2) + row * AST2 + ch * 8;
            }
            unsigned ss = (unsigned)__cvta_generic_to_shared(s);
            asm volatile("cp.async.cg.shared.global [%0], [%1], 16;"
                         :: "r"(ss), "l"(g));
        }
        asm volatile("cp.async.commit_group;");
    };

    // prologue: stages 0..2 in flight
    prefetch(0);
    prefetch(1);
    prefetch(2);

    for (int kt = 0; kt < KITERS; kt++) {
        if (kt + 3 < KITERS) prefetch(kt + 3);
        else asm volatile("cp.async.commit_group;");   // keep group count invariant
        asm volatile("cp.async.wait_group 3;");
        __syncthreads();

        __half* st  = sm + (kt & (NSTAGE - 1)) * STAGE_HALVES;
        __half* Ash = st;
        __half* Asl = st + 128 * AST2;
        __half* Bsh = st + 256 * AST2;
        __half* Bsl = st + 256 * AST2 + 112 * AST2;

        // A fragments (hi, lo): 2 m16 tiles each, ldmatrix.x4 non-trans
        unsigned afh[2][4], afl[2][4];
#pragma unroll
        for (int mt = 0; mt < 2; mt++) {
            int arow = wm * 32 + mt * 16 + (lane & 15);
            int acol = (lane >> 4) << 3;
            unsigned sa = (unsigned)__cvta_generic_to_shared(Ash + arow * AST2 + acol);
            asm volatile("ldmatrix.sync.aligned.m8n8.x4.shared.b16 {%0,%1,%2,%3}, [%4];"
                         : "=r"(afh[mt][0]), "=r"(afh[mt][1]), "=r"(afh[mt][2]), "=r"(afh[mt][3])
                         : "r"(sa));
            unsigned sal = (unsigned)__cvta_generic_to_shared(Asl + arow * AST2 + acol);
            asm volatile("ldmatrix.sync.aligned.m8n8.x4.shared.b16 {%0,%1,%2,%3}, [%4];"
                         : "=r"(afl[mt][0]), "=r"(afl[mt][1]), "=r"(afl[mt][2]), "=r"(afl[mt][3])
                         : "r"(sal));
        }
        // B fragments (hi, lo): 7 n8 tiles; 3 x4 (pairs) + 1 x2
        unsigned bfh[7][2], bfl[7][2];
#pragma unroll
        for (int p = 0; p < 3; p++) {
            int brow = wn * 56 + p * 16 + (lane & 7) + ((lane & 16) >> 1);
            int bcol = lane & 8;
            unsigned sb = (unsigned)__cvta_generic_to_shared(Bsh + brow * AST2 + bcol);
            asm volatile("ldmatrix.sync.aligned.m8n8.x4.shared.b16 {%0,%1,%2,%3}, [%4];"
                         : "=r"(bfh[2*p][0]), "=r"(bfh[2*p][1]), "=r"(bfh[2*p+1][0]), "=r"(bfh[2*p+1][1])
                         : "r"(sb));
            unsigned sbl = (unsigned)__cvta_generic_to_shared(Bsl + brow * AST2 + bcol);
            asm volatile("ldmatrix.sync.aligned.m8n8.x4.shared.b16 {%0,%1,%2,%3}, [%4];"
                         : "=r"(bfl[2*p][0]), "=r"(bfl[2*p][1]), "=r"(bfl[2*p+1][0]), "=r"(bfl[2*p+1][1])
                         : "r"(sbl));
        }
        {
            int brow = wn * 56 + 48 + (lane & 7);
            int bcol = lane & 8;
            unsigned sb = (unsigned)__cvta_generic_to_shared(Bsh + brow * AST2 + bcol);
            asm volatile("ldmatrix.sync.aligned.m8n8.x2.shared.b16 {%0,%1}, [%2];"
                         : "=r"(bfh[6][0]), "=r"(bfh[6][1]) : "r"(sb));
            unsigned sbl = (unsigned)__cvta_generic_to_shared(Bsl + brow * AST2 + bcol);
            asm volatile("ldmatrix.sync.aligned.m8n8.x2.shared.b16 {%0,%1}, [%2];"
                         : "=r"(bfl[6][0]), "=r"(bfl[6][1]) : "r"(sbl));
        }
#pragma unroll
        for (int mt = 0; mt < 2; mt++)
#pragma unroll
            for (int nt = 0; nt < 7; nt++) {
                asm volatile(
                    "mma.sync.aligned.m16n8k16.row.col.f32.f16.f16.f32 "
                    "{%0,%1,%2,%3}, {%4,%5,%6,%7}, {%8,%9}, {%0,%1,%2,%3};"
                    : "+f"(acc[mt][nt][0]), "+f"(acc[mt][nt][1]),
                      "+f"(acc[mt][nt][2]), "+f"(acc[mt][nt][3])
                    : "r"(afh[mt][0]), "r"(afh[mt][1]), "r"(afh[mt][2]), "r"(afh[mt][3]),
                      "r"(bfh[nt][0]), "r"(bfh[nt][1]));
                asm volatile(
                    "mma.sync.aligned.m16n8k16.row.col.f32.f16.f16.f32 "
                    "{%0,%1,%2,%3}, {%4,%5,%6,%7}, {%8,%9}, {%0,%1,%2,%3};"
                    : "+f"(acc[mt][nt][0]), "+f"(acc[mt][nt][1]),
                      "+f"(acc[mt][nt][2]), "+f"(acc[mt][nt][3])
                    : "r"(afh[mt][0]), "r"(afh[mt][1]), "r"(afh[mt][2]), "r"(afh[mt][3]),
                      "r"(bfl[nt][0]), "r"(bfl[nt][1]));
                asm volatile(
                    "mma.sync.aligned.m16n8k16.row.col.f32.f16.f16.f32 "
                    "{%0,%1,%2,%3}, {%4,%5,%6,%7}, {%8,%9}, {%0,%1,%2,%3};"
                    : "+f"(acc[mt][nt][0]), "+f"(acc[mt][nt][1]),
                      "+f"(acc[mt][nt][2]), "+f"(acc[mt][nt][3])
                    : "r"(afl[mt][0]), "r"(afl[mt][1]), "r"(afl[mt][2]), "r"(afl[mt][3]),
                      "r"(bfh[nt][0]), "r"(bfh[nt][1]));
            }
        __syncthreads();
    }

    // epilogue: C frag lane mapping m16n8: row = l/4 (+8), col = (l%4)*2 (+1)
#pragma unroll
    for (int mt = 0; mt < 2; mt++) {
#pragma unroll
        for (int nt = 0; nt < 7; nt++) {
            int row = m0 + wm * 32 + mt * 16 + (lane >> 2);
            int col = n0 + wn * 56 + nt * 8 + (lane & 3) * 2;
            float b0 = bias[col], b1 = bias[col + 1];
            float2 v0 = make_float2(acc[mt][nt][0] + b0, acc[mt][nt][1] + b1);
            float2 v1 = make_float2(acc[mt][nt][2] + b0, acc[mt][nt][3] + b1);
            *(float2*)(Y + (size_t)row * CC + col) = v0;
            *(float2*)(Y + (size_t)(row + 8) * CC + col) = v1;
        }
    }
}

// ---------------- logits: L[bh][n][m] = (Q@K^T)/14 + cp@Q (fp32 SIMT) ------
__global__ __launch_bounds__(196) void attn_logits_kernel()
{
    __shared__ float As[14][98];
    __shared__ float Bs[14][98];
    const int t  = threadIdx.x;
    const int bh = blockIdx.z;
    const int b  = bh / HH, h = bh % HH;
    const int n0 = blockIdx.y * 98;
    const int m0 = blockIdx.x * 98;
    const int tx = t % 14, ty = t / 14;

    const float* Qb = g_Q + (size_t)b * NN * CC + h * DD;
    const float* Kb = g_K + (size_t)b * NN * CC + h * DD;

    float acc[7][7];
#pragma unroll
    for (int i = 0; i < 7; i++)
#pragma unroll
        for (int j = 0; j < 7; j++) acc[i][j] = 0.f;

    for (int k0 = 0; k0 < DD; k0 += 14) {
        for (int v = t; v < 1372; v += 196) {
            int r = v / 14, c = v - r * 14;
            As[c][r] = Qb[(size_t)(n0 + r) * CC + k0 + c];
            Bs[c][r] = Kb[(size_t)(m0 + r) * CC + k0 + c];
        }
        __syncthreads();
#pragma unroll
        for (int kk = 0; kk < 14; kk++) {
            float a[7], bb[7];
#pragma unroll
            for (int i = 0; i < 7; i++) a[i]  = As[kk][ty * 7 + i];
#pragma unroll
            for (int j = 0; j < 7; j++) bb[j] = Bs[kk][tx * 7 + j];
#pragma unroll
            for (int i = 0; i < 7; i++)
#pragma unroll
                for (int j = 0; j < 7; j++)
                    acc[i][j] = fmaf(a[i], bb[j], acc[i][j]);
        }
        __syncthreads();
    }
#pragma unroll
    for (int i = 0; i < 7; i++)
#pragma unroll
        for (int j = 0; j < 7; j++) acc[i][j] *= (1.0f / 14.0f);

    const float* cpb = g_CP + h * NN * DD;
    for (int k0 = 0; k0 < NN; k0 += 14) {
        for (int v = t; v < 1372; v += 196) {
            int r = v / 14, c = v - r * 14;
            As[c][r] = cpb[(n0 + r) * DD + k0 + c];
        }
        for (int v = t; v < 1372; v += 196) {
            int kr = v / 98, mc = v - kr * 98;
            Bs[kr][mc] = Qb[(size_t)(k0 + kr) * CC + m0 + mc];
        }
        __syncthreads();
#pragma unroll
        for (int kk = 0; kk < 14; kk++) {
            float a[7], bb[7];
#pragma unroll
            for (int i = 0; i < 7; i++) a[i]  = As[kk][ty * 7 + i];
#pragma unroll
            for (int j = 0; j < 7; j++) bb[j] = Bs[kk][tx * 7 + j];
#pragma unroll
            for (int i = 0; i < 7; i++)
#pragma unroll
                for (int j = 0; j < 7; j++)
                    acc[i][j] = fmaf(a[i], bb[j], acc[i][j]);
        }
        __syncthreads();
    }

    float* Lb = g_L + (size_t)bh * NN * NN;
#pragma unroll
    for (int i = 0; i < 7; i++)
#pragma unroll
        for (int j = 0; j < 7; j++)
            Lb[(size_t)(n0 + ty * 7 + i) * NN + m0 + tx * 7 + j] = acc[i][j];
}

// ---------------- softmax: one warp per 196-wide row ------------------------
__global__ __launch_bounds__(256) void softmax_kernel()
{
    const int warp = threadIdx.x >> 5, lane = threadIdx.x & 31;
    const size_t row = (size_t)blockIdx.x * 8 + warp;
    float* p = g_L + row * NN;

    float v[7];
    float mx = -1e30f;
#pragma unroll
    for (int s = 0; s < 7; s++) {
        int idx = lane + s * 32;
        v[s] = (idx < NN) ? p[idx] : -1e30f;
        mx = fmaxf(mx, v[s]);
    }
#pragma unroll
    for (int o = 16; o; o >>= 1) mx = fmaxf(mx, __shfl_xor_sync(0xffffffffu, mx, o));
    float sum = 0.f;
#pragma unroll
    for (int s = 0; s < 7; s++) { v[s] = __expf(v[s] - mx); sum += v[s]; }
#pragma unroll
    for (int o = 16; o; o >>= 1) sum += __shfl_xor_sync(0xffffffffu, sum, o);
    float inv = 1.0f / sum;
#pragma unroll
    for (int s = 0; s < 7; s++) {
        int idx = lane + s * 32;
        if (idx < NN) p[idx] = v[s] * inv;
    }
}

// ---------------- out = attn @ V, stored hi/lo fp16 into (B,N,C) ------------
__global__ __launch_bounds__(196) void attn_v_kernel()
{
    __shared__ float As[14][98];
    __shared__ float Bs[14][98];
    const int t  = threadIdx.x;
    const int bh = blockIdx.z;
    const int b  = bh / HH, h = bh % HH;
    const int n0 = blockIdx.y * 98;
    const int c0 = blockIdx.x * 98;
    const int tx = t % 14, ty = t / 14;

    const float* Lb = g_L + (size_t)bh * NN * NN;
    const float* Vb = g_V + (size_t)b * NN * CC + h * DD;

    float acc[7][7];
#pragma unroll
    for (int i = 0; i < 7; i++)
#pragma unroll
        for (int j = 0; j < 7; j++) acc[i][j] = 0.f;

    for (int m0 = 0; m0 < NN; m0 += 14) {
        for (int v = t; v < 1372; v += 196) {
            int r = v / 14, c = v - r * 14;
            As[c][r] = Lb[(size_t)(n0 + r) * NN + m0 + c];
        }
        for (int v = t; v < 1372; v += 196) {
            int kr = v / 98, mc = v - kr * 98;
            Bs[kr][mc] = Vb[(size_t)(m0 + kr) * CC + c0 + mc];
        }
        __syncthreads();
#pragma unroll
        for (int kk = 0; kk < 14; kk++) {
            float a[7], bb[7];
#pragma unroll
            for (int i = 0; i < 7; i++) a[i]  = As[kk][ty * 7 + i];
#pragma unroll
            for (int j = 0; j < 7; j++) bb[j] = Bs[kk][tx * 7 + j];
#pragma unroll
            for (int i = 0; i < 7; i++)
#pragma unroll
                for (int j = 0; j < 7; j++)
                    acc[i][j] = fmaf(a[i], bb[j], acc[i][j]);
        }
        __syncthreads();
    }

    __half* Oh = g_Oh + (size_t)b * NN * CC + h * DD;
    __half* Ol = g_Ol + (size_t)b * NN * CC + h * DD;
#pragma unroll
    for (int i = 0; i < 7; i++)
#pragma unroll
        for (int j = 0; j < 7; j++) {
            float  f = acc[i][j];
            __half h2 = __float2half_rn(f);
            size_t off = (size_t)(n0 + ty * 7 + i) * CC + c0 + tx * 7 + j;
            Oh[off] = h2;
            Ol[off] = __float2half_rn(f - __half2float(h2));
        }
}

// ---------------- launcher --------------------------------------------------
extern "C" void kernel_launch(void* const* d_in, const int* in_sizes, int n_in,
                              void* d_out, int out_size)
{
    const float* x     = (const float*)d_in[0];
    const float* Wq    = (const float*)d_in[1];
    const float* bq    = (const float*)d_in[2];
    const float* Wk    = (const float*)d_in[3];
    const float* bk    = (const float*)d_in[4];
    const float* Wv    = (const float*)d_in[5];
    const float* bv    = (const float*)d_in[6];
    const float* Wo    = (const float*)d_in[7];
    const float* bo    = (const float*)d_in[8];
    const float* rel_h = (const float*)d_in[9];
    const float* rel_w = (const float*)d_in[10];
    float* out = (float*)d_out;

    float  *pQ, *pK, *pV;
    __half *pXh, *pXl, *pOh, *pOl, *pWh, *pWl;
    cudaGetSymbolAddress((void**)&pQ,  g_Q);
    cudaGetSymbolAddress((void**)&pK,  g_K);
    cudaGetSymbolAddress((void**)&pV,  g_V);
    cudaGetSymbolAddress((void**)&pXh, g_Xh);
    cudaGetSymbolAddress((void**)&pXl, g_Xl);
    cudaGetSymbolAddress((void**)&pOh, g_Oh);
    cudaGetSymbolAddress((void**)&pOl, g_Ol);
    cudaGetSymbolAddress((void**)&pWh, g_Wh);
    cudaGetSymbolAddress((void**)&pWl, g_Wl);

    const unsigned smem = NSTAGE * STAGE_HALVES * sizeof(__half);  // 92160 B
    cudaFuncSetAttribute(hgemm_proj3,
        cudaFuncAttributeMaxDynamicSharedMemorySize, smem);

    // hi/lo splits
    const int xn = MM * CC;
    const int wn = CC * CC;
    f2h_split_kernel<<<(xn + 255) / 256, 256>>>(x,  pXh,          pXl,          xn);
    f2h_split_kernel<<<(wn + 255) / 256, 256>>>(Wq, pWh + 0 * wn, pWl + 0 * wn, wn);
    f2h_split_kernel<<<(wn + 255) / 256, 256>>>(Wk, pWh + 1 * wn, pWl + 1 * wn, wn);
    f2h_split_kernel<<<(wn + 255) / 256, 256>>>(Wv, pWh + 2 * wn, pWl + 2 * wn, wn);
    f2h_split_kernel<<<(wn + 255) / 256, 256>>>(Wo, pWh + 3 * wn, pWl + 3 * wn, wn);

    cp_kernel<<<(HH * NN * DD + 255) / 256, 256>>>(rel_h, rel_w);

    dim3 pgrid(CC / 112, MM / 128);   // (7, 392)
    hgemm_proj3<<<pgrid, 256, smem>>>(pXh, pXl, pWh + 0 * wn, pWl + 0 * wn, bq, pQ);
    hgemm_proj3<<<pgrid, 256, smem>>>(pXh, pXl, pWh + 1 * wn, pWl + 1 * wn, bk, pK);
    hgemm_proj3<<<pgrid, 256, smem>>>(pXh, pXl, pWh + 2 * wn, pWl + 2 * wn, bv, pV);

    attn_logits_kernel<<<dim3(2, 2, BB * HH), 196>>>();
    softmax_kernel<<<BB * HH * NN / 8, 256>>>();
    attn_v_kernel<<<dim3(2, 2, BB * HH), 196>>>();

    hgemm_proj3<<<pgrid, 256, smem>>>(pOh, pOl, pWh + 3 * wn, pWl + 3 * wn, bo, out);
}

// round 6
// speedup vs baseline: 2.3930x; 1.2421x over previous
#include <cuda_runtime.h>
#include <cuda_fp16.h>
#include <math.h>

#define BB 256
#define NN 196
#define CC 784
#define HH 4
#define DD 196
#define MM (BB*NN)          // 50176 tokens

// ---------------- scratch (device globals: allocation-free rule) ------------
__device__ __align__(16) float  g_Q[(size_t)MM * CC];
__device__ __align__(16) float  g_K[(size_t)MM * CC];
__device__ __align__(16) float  g_V[(size_t)MM * CC];
__device__ __align__(16) float  g_L[(size_t)BB * HH * NN * NN];
__device__ __align__(16) float  g_CP[HH * NN * DD];
__device__ __align__(16) __half g_Xh[(size_t)MM * CC];          // x hi
__device__ __align__(16) __half g_Xl[(size_t)MM * CC];          // x lo
__device__ __align__(16) __half g_Oh[(size_t)MM * CC];          // attn out hi
__device__ __align__(16) __half g_Wqh[CC * CC];
__device__ __align__(16) __half g_Wql[CC * CC];
__device__ __align__(16) __half g_Wkh[CC * CC];
__device__ __align__(16) __half g_Wvh[CC * CC];
__device__ __align__(16) __half g_Woh[CC * CC];

// ---------------- f32 -> (f16 hi, f16 lo) split -----------------------------
__global__ void f2h_split_kernel(const float* __restrict__ in,
                                 __half* __restrict__ hi,
                                 __half* __restrict__ lo, int n) {
    int i = blockIdx.x * blockDim.x + threadIdx.x;
    if (i >= n) return;
    float f = in[i];
    __half h = __float2half_rn(f);
    hi[i] = h;
    lo[i] = __float2half_rn(f - __half2float(h));
}

// ---------------- f32 -> f16 (hi only) --------------------------------------
__global__ void f2h_hi_kernel(const float* __restrict__ in,
                              __half* __restrict__ hi, int n) {
    int i = blockIdx.x * blockDim.x + threadIdx.x;
    if (i >= n) return;
    hi[i] = __float2half_rn(in[i]);
}

// ---------------- cp[h][p][k] = rel_h[h,k,p/14] + rel_w[h,k,p%14] ----------
__global__ void cp_kernel(const float* __restrict__ rel_h,
                          const float* __restrict__ rel_w) {
    int idx = blockIdx.x * blockDim.x + threadIdx.x;
    if (idx >= HH * NN * DD) return;
    int h   = idx / (NN * DD);
    int rem = idx - h * (NN * DD);
    int p   = rem / DD;
    int k   = rem - p * DD;
    g_CP[idx] = rel_h[(h * DD + k) * 14 + (p / 14)]
              + rel_w[(h * DD + k) * 14 + (p % 14)];
}

#define AST2 24                      // halves per smem row (48B, conflict-free)
#define NSTAGE 4
#define KITERS 49                    // 784 / 16

// ============ 3-term split-fp16 HMMA GEMM (used for Q projection) ===========
#define STG3 ((128 + 128 + 112 + 112) * AST2)   // 11520 halves

__global__ __launch_bounds__(256) void hgemm_proj3(
    const __half* __restrict__ Ah, const __half* __restrict__ Al,
    const __half* __restrict__ Wh, const __half* __restrict__ Wl,
    const float* __restrict__ bias, float* __restrict__ Y)
{
    extern __shared__ __half sm[];
    const int t    = threadIdx.x;
    const int lane = t & 31;
    const int wid  = t >> 5;
    const int wm   = wid & 3;
    const int wn   = wid >> 2;
    const int m0   = blockIdx.y * 128;
    const int n0   = blockIdx.x * 112;

    float acc[2][7][4];
#pragma unroll
    for (int i = 0; i < 2; i++)
#pragma unroll
        for (int j = 0; j < 7; j++)
#pragma unroll
            for (int r = 0; r < 4; r++) acc[i][j][r] = 0.f;

    auto prefetch = [&](int kt) {
        const int k0 = kt * 16;
        __half* st = sm + (kt & (NSTAGE - 1)) * STG3;
        for (int v = t; v < 960; v += 256) {
            const __half* g;
            __half* s;
            if (v < 512) {
                int part = v >> 8, rem = v & 255;
                int row = rem >> 1, ch = rem & 1;
                g = (part ? Al : Ah) + (size_t)(m0 + row) * CC + k0 + ch * 8;
                s = st + part * (128 * AST2) + row * AST2 + ch * 8;
            } else {
                int v2 = v - 512;
                int part = v2 / 224, rem = v2 % 224;
                int row = rem >> 1, ch = rem & 1;
                g = (part ? Wl : Wh) + (size_t)(n0 + row) * CC + k0 + ch * 8;
                s = st + 256 * AST2 + part * (112 * AST2) + row * AST2 + ch * 8;
            }
            unsigned ss = (unsigned)__cvta_generic_to_shared(s);
            asm volatile("cp.async.cg.shared.global [%0], [%1], 16;"
                         :: "r"(ss), "l"(g));
        }
        asm volatile("cp.async.commit_group;");
    };

    prefetch(0); prefetch(1); prefetch(2);

    for (int kt = 0; kt < KITERS; kt++) {
        if (kt + 3 < KITERS) prefetch(kt + 3);
        else asm volatile("cp.async.commit_group;");
        asm volatile("cp.async.wait_group 3;");
        __syncthreads();

        __half* st  = sm + (kt & (NSTAGE - 1)) * STG3;
        __half* Ash = st;
        __half* Asl = st + 128 * AST2;
        __half* Bsh = st + 256 * AST2;
        __half* Bsl = st + 256 * AST2 + 112 * AST2;

        unsigned afh[2][4], afl[2][4];
#pragma unroll
        for (int mt = 0; mt < 2; mt++) {
            int arow = wm * 32 + mt * 16 + (lane & 15);
            int acol = (lane >> 4) << 3;
            unsigned sa = (unsigned)__cvta_generic_to_shared(Ash + arow * AST2 + acol);
            asm volatile("ldmatrix.sync.aligned.m8n8.x4.shared.b16 {%0,%1,%2,%3}, [%4];"
                         : "=r"(afh[mt][0]), "=r"(afh[mt][1]), "=r"(afh[mt][2]), "=r"(afh[mt][3])
                         : "r"(sa));
            unsigned sal = (unsigned)__cvta_generic_to_shared(Asl + arow * AST2 + acol);
            asm volatile("ldmatrix.sync.aligned.m8n8.x4.shared.b16 {%0,%1,%2,%3}, [%4];"
                         : "=r"(afl[mt][0]), "=r"(afl[mt][1]), "=r"(afl[mt][2]), "=r"(afl[mt][3])
                         : "r"(sal));
        }
        unsigned bfh[7][2], bfl[7][2];
#pragma unroll
        for (int p = 0; p < 3; p++) {
            int brow = wn * 56 + p * 16 + (lane & 7) + ((lane & 16) >> 1);
            int bcol = lane & 8;
            unsigned sb = (unsigned)__cvta_generic_to_shared(Bsh + brow * AST2 + bcol);
            asm volatile("ldmatrix.sync.aligned.m8n8.x4.shared.b16 {%0,%1,%2,%3}, [%4];"
                         : "=r"(bfh[2*p][0]), "=r"(bfh[2*p][1]), "=r"(bfh[2*p+1][0]), "=r"(bfh[2*p+1][1])
                         : "r"(sb));
            unsigned sbl = (unsigned)__cvta_generic_to_shared(Bsl + brow * AST2 + bcol);
            asm volatile("ldmatrix.sync.aligned.m8n8.x4.shared.b16 {%0,%1,%2,%3}, [%4];"
                         : "=r"(bfl[2*p][0]), "=r"(bfl[2*p][1]), "=r"(bfl[2*p+1][0]), "=r"(bfl[2*p+1][1])
                         : "r"(sbl));
        }
        {
            int brow = wn * 56 + 48 + (lane & 7);
            int bcol = lane & 8;
            unsigned sb = (unsigned)__cvta_generic_to_shared(Bsh + brow * AST2 + bcol);
            asm volatile("ldmatrix.sync.aligned.m8n8.x2.shared.b16 {%0,%1}, [%2];"
                         : "=r"(bfh[6][0]), "=r"(bfh[6][1]) : "r"(sb));
            unsigned sbl = (unsigned)__cvta_generic_to_shared(Bsl + brow * AST2 + bcol);
            asm volatile("ldmatrix.sync.aligned.m8n8.x2.shared.b16 {%0,%1}, [%2];"
                         : "=r"(bfl[6][0]), "=r"(bfl[6][1]) : "r"(sbl));
        }
#pragma unroll
        for (int mt = 0; mt < 2; mt++)
#pragma unroll
            for (int nt = 0; nt < 7; nt++) {
                asm volatile(
                    "mma.sync.aligned.m16n8k16.row.col.f32.f16.f16.f32 "
                    "{%0,%1,%2,%3}, {%4,%5,%6,%7}, {%8,%9}, {%0,%1,%2,%3};"
                    : "+f"(acc[mt][nt][0]), "+f"(acc[mt][nt][1]),
                      "+f"(acc[mt][nt][2]), "+f"(acc[mt][nt][3])
                    : "r"(afh[mt][0]), "r"(afh[mt][1]), "r"(afh[mt][2]), "r"(afh[mt][3]),
                      "r"(bfh[nt][0]), "r"(bfh[nt][1]));
                asm volatile(
                    "mma.sync.aligned.m16n8k16.row.col.f32.f16.f16.f32 "
                    "{%0,%1,%2,%3}, {%4,%5,%6,%7}, {%8,%9}, {%0,%1,%2,%3};"
                    : "+f"(acc[mt][nt][0]), "+f"(acc[mt][nt][1]),
                      "+f"(acc[mt][nt][2]), "+f"(acc[mt][nt][3])
                    : "r"(afh[mt][0]), "r"(afh[mt][1]), "r"(afh[mt][2]), "r"(afh[mt][3]),
                      "r"(bfl[nt][0]), "r"(bfl[nt][1]));
                asm volatile(
                    "mma.sync.aligned.m16n8k16.row.col.f32.f16.f16.f32 "
                    "{%0,%1,%2,%3}, {%4,%5,%6,%7}, {%8,%9}, {%0,%1,%2,%3};"
                    : "+f"(acc[mt][nt][0]), "+f"(acc[mt][nt][1]),
                      "+f"(acc[mt][nt][2]), "+f"(acc[mt][nt][3])
                    : "r"(afl[mt][0]), "r"(afl[mt][1]), "r"(afl[mt][2]), "r"(afl[mt][3]),
                      "r"(bfh[nt][0]), "r"(bfh[nt][1]));
            }
        __syncthreads();
    }

#pragma unroll
    for (int mt = 0; mt < 2; mt++) {
#pragma unroll
        for (int nt = 0; nt < 7; nt++) {
            int row = m0 + wm * 32 + mt * 16 + (lane >> 2);
            int col = n0 + wn * 56 + nt * 8 + (lane & 3) * 2;
            float b0 = bias[col], b1 = bias[col + 1];
            float2 v0 = make_float2(acc[mt][nt][0] + b0, acc[mt][nt][1] + b1);
            float2 v1 = make_float2(acc[mt][nt][2] + b0, acc[mt][nt][3] + b1);
            *(float2*)(Y + (size_t)row * CC + col) = v0;
            *(float2*)(Y + (size_t)(row + 8) * CC + col) = v1;
        }
    }
}

// ============ 1-term fp16 HMMA GEMM (K, V, O projections) ===================
#define STG1 ((128 + 112) * AST2)    // 5760 halves = 11520 B

__global__ __launch_bounds__(256) void hgemm_proj1(
    const __half* __restrict__ Ah, const __half* __restrict__ Wh,
    const float* __restrict__ bias, float* __restrict__ Y)
{
    extern __shared__ __half sm[];
    const int t    = threadIdx.x;
    const int lane = t & 31;
    const int wid  = t >> 5;
    const int wm   = wid & 3;
    const int wn   = wid >> 2;
    const int m0   = blockIdx.y * 128;
    const int n0   = blockIdx.x * 112;

    float acc[2][7][4];
#pragma unroll
    for (int i = 0; i < 2; i++)
#pragma unroll
        for (int j = 0; j < 7; j++)
#pragma unroll
            for (int r = 0; r < 4; r++) acc[i][j][r] = 0.f;

    auto prefetch = [&](int kt) {
        const int k0 = kt * 16;
        __half* st = sm + (kt & (NSTAGE - 1)) * STG1;
        for (int v = t; v < 480; v += 256) {
            const __half* g;
            __half* s;
            if (v < 256) {
                int row = v >> 1, ch = v & 1;
                g = Ah + (size_t)(m0 + row) * CC + k0 + ch * 8;
                s = st + row * AST2 + ch * 8;
            } else {
                int v2 = v - 256;
                int row = v2 >> 1, ch = v2 & 1;
                g = Wh + (size_t)(n0 + row) * CC + k0 + ch * 8;
                s = st + 128 * AST2 + row * AST2 + ch * 8;
            }
            unsigned ss = (unsigned)__cvta_generic_to_shared(s);
            asm volatile("cp.async.cg.shared.global [%0], [%1], 16;"
                         :: "r"(ss), "l"(g));
        }
        asm volatile("cp.async.commit_group;");
    };

    prefetch(0); prefetch(1); prefetch(2);

    for (int kt = 0; kt < KITERS; kt++) {
        if (kt + 3 < KITERS) prefetch(kt + 3);
        else asm volatile("cp.async.commit_group;");
        asm volatile("cp.async.wait_group 3;");
        __syncthreads();

        __half* st  = sm + (kt & (NSTAGE - 1)) * STG1;
        __half* Ash = st;
        __half* Bsh = st + 128 * AST2;

        unsigned afh[2][4];
#pragma unroll
        for (int mt = 0; mt < 2; mt++) {
            int arow = wm * 32 + mt * 16 + (lane & 15);
            int acol = (lane >> 4) << 3;
            unsigned sa = (unsigned)__cvta_generic_to_shared(Ash + arow * AST2 + acol);
            asm volatile("ldmatrix.sync.aligned.m8n8.x4.shared.b16 {%0,%1,%2,%3}, [%4];"
                         : "=r"(afh[mt][0]), "=r"(afh[mt][1]), "=r"(afh[mt][2]), "=r"(afh[mt][3])
                         : "r"(sa));
        }
        unsigned bfh[7][2];
#pragma unroll
        for (int p = 0; p < 3; p++) {
            int brow = wn * 56 + p * 16 + (lane & 7) + ((lane & 16) >> 1);
            int bcol = lane & 8;
            unsigned sb = (unsigned)__cvta_generic_to_shared(Bsh + brow * AST2 + bcol);
            asm volatile("ldmatrix.sync.aligned.m8n8.x4.shared.b16 {%0,%1,%2,%3}, [%4];"
                         : "=r"(bfh[2*p][0]), "=r"(bfh[2*p][1]), "=r"(bfh[2*p+1][0]), "=r"(bfh[2*p+1][1])
                         : "r"(sb));
        }
        {
            int brow = wn * 56 + 48 + (lane & 7);
            int bcol = lane & 8;
            unsigned sb = (unsigned)__cvta_generic_to_shared(Bsh + brow * AST2 + bcol);
            asm volatile("ldmatrix.sync.aligned.m8n8.x2.shared.b16 {%0,%1}, [%2];"
                         : "=r"(bfh[6][0]), "=r"(bfh[6][1]) : "r"(sb));
        }
#pragma unroll
        for (int mt = 0; mt < 2; mt++)
#pragma unroll
            for (int nt = 0; nt < 7; nt++) {
                asm volatile(
                    "mma.sync.aligned.m16n8k16.row.col.f32.f16.f16.f32 "
                    "{%0,%1,%2,%3}, {%4,%5,%6,%7}, {%8,%9}, {%0,%1,%2,%3};"
                    : "+f"(acc[mt][nt][0]), "+f"(acc[mt][nt][1]),
                      "+f"(acc[mt][nt][2]), "+f"(acc[mt][nt][3])
                    : "r"(afh[mt][0]), "r"(afh[mt][1]), "r"(afh[mt][2]), "r"(afh[mt][3]),
                      "r"(bfh[nt][0]), "r"(bfh[nt][1]));
            }
        __syncthreads();
    }

#pragma unroll
    for (int mt = 0; mt < 2; mt++) {
#pragma unroll
        for (int nt = 0; nt < 7; nt++) {
            int row = m0 + wm * 32 + mt * 16 + (lane >> 2);
            int col = n0 + wn * 56 + nt * 8 + (lane & 3) * 2;
            float b0 = bias[col], b1 = bias[col + 1];
            float2 v0 = make_float2(acc[mt][nt][0] + b0, acc[mt][nt][1] + b1);
            float2 v1 = make_float2(acc[mt][nt][2] + b0, acc[mt][nt][3] + b1);
            *(float2*)(Y + (size_t)row * CC + col) = v0;
            *(float2*)(Y + (size_t)(row + 8) * CC + col) = v1;
        }
    }
}

// ---------------- logits: L[bh][n][m] = (Q@K^T)/14 + cp@Q (fp32 SIMT) ------
__global__ __launch_bounds__(196) void attn_logits_kernel()
{
    __shared__ float As[14][98];
    __shared__ float Bs[14][98];
    const int t  = threadIdx.x;
    const int bh = blockIdx.z;
    const int b  = bh / HH, h = bh % HH;
    const int n0 = blockIdx.y * 98;
    const int m0 = blockIdx.x * 98;
    const int tx = t % 14, ty = t / 14;

    const float* Qb = g_Q + (size_t)b * NN * CC + h * DD;
    const float* Kb = g_K + (size_t)b * NN * CC + h * DD;

    float acc[7][7];
#pragma unroll
    for (int i = 0; i < 7; i++)
#pragma unroll
        for (int j = 0; j < 7; j++) acc[i][j] = 0.f;

    for (int k0 = 0; k0 < DD; k0 += 14) {
        for (int v = t; v < 1372; v += 196) {
            int r = v / 14, c = v - r * 14;
            As[c][r] = Qb[(size_t)(n0 + r) * CC + k0 + c];
            Bs[c][r] = Kb[(size_t)(m0 + r) * CC + k0 + c];
        }
        __syncthreads();
#pragma unroll
        for (int kk = 0; kk < 14; kk++) {
            float a[7], bb[7];
#pragma unroll
            for (int i = 0; i < 7; i++) a[i]  = As[kk][ty * 7 + i];
#pragma unroll
            for (int j = 0; j < 7; j++) bb[j] = Bs[kk][tx * 7 + j];
#pragma unroll
            for (int i = 0; i < 7; i++)
#pragma unroll
                for (int j = 0; j < 7; j++)
                    acc[i][j] = fmaf(a[i], bb[j], acc[i][j]);
        }
        __syncthreads();
    }
#pragma unroll
    for (int i = 0; i < 7; i++)
#pragma unroll
        for (int j = 0; j < 7; j++) acc[i][j] *= (1.0f / 14.0f);

    const float* cpb = g_CP + h * NN * DD;
    for (int k0 = 0; k0 < NN; k0 += 14) {
        for (int v = t; v < 1372; v += 196) {
            int r = v / 14, c = v - r * 14;
            As[c][r] = cpb[(n0 + r) * DD + k0 + c];
        }
        for (int v = t; v < 1372; v += 196) {
            int kr = v / 98, mc = v - kr * 98;
            Bs[kr][mc] = Qb[(size_t)(k0 + kr) * CC + m0 + mc];
        }
        __syncthreads();
#pragma unroll
        for (int kk = 0; kk < 14; kk++) {
            float a[7], bb[7];
#pragma unroll
            for (int i = 0; i < 7; i++) a[i]  = As[kk][ty * 7 + i];
#pragma unroll
            for (int j = 0; j < 7; j++) bb[j] = Bs[kk][tx * 7 + j];
#pragma unroll
            for (int i = 0; i < 7; i++)
#pragma unroll
                for (int j = 0; j < 7; j++)
                    acc[i][j] = fmaf(a[i], bb[j], acc[i][j]);
        }
        __syncthreads();
    }

    float* Lb = g_L + (size_t)bh * NN * NN;
#pragma unroll
    for (int i = 0; i < 7; i++)
#pragma unroll
        for (int j = 0; j < 7; j++)
            Lb[(size_t)(n0 + ty * 7 + i) * NN + m0 + tx * 7 + j] = acc[i][j];
}

// ---------------- softmax: one warp per 196-wide row ------------------------
__global__ __launch_bounds__(256) void softmax_kernel()
{
    const int warp = threadIdx.x >> 5, lane = threadIdx.x & 31;
    const size_t row = (size_t)blockIdx.x * 8 + warp;
    float* p = g_L + row * NN;

    float v[7];
    float mx = -1e30f;
#pragma unroll
    for (int s = 0; s < 7; s++) {
        int idx = lane + s * 32;
        v[s] = (idx < NN) ? p[idx] : -1e30f;
        mx = fmaxf(mx, v[s]);
    }
#pragma unroll
    for (int o = 16; o; o >>= 1) mx = fmaxf(mx, __shfl_xor_sync(0xffffffffu, mx, o));
    float sum = 0.f;
#pragma unroll
    for (int s = 0; s < 7; s++) { v[s] = __expf(v[s] - mx); sum += v[s]; }
#pragma unroll
    for (int o = 16; o; o >>= 1) sum += __shfl_xor_sync(0xffffffffu, sum, o);
    float inv = 1.0f / sum;
#pragma unroll
    for (int s = 0; s < 7; s++) {
        int idx = lane + s * 32;
        if (idx < NN) p[idx] = v[s] * inv;
    }
}

// ---------------- out = attn @ V, stored fp16 hi into (B,N,C) ---------------
__global__ __launch_bounds__(196) void attn_v_kernel()
{
    __shared__ float As[14][98];
    __shared__ float Bs[14][98];
    const int t  = threadIdx.x;
    const int bh = blockIdx.z;
    const int b  = bh / HH, h = bh % HH;
    const int n0 = blockIdx.y * 98;
    const int c0 = blockIdx.x * 98;
    const int tx = t % 14, ty = t / 14;

    const float* Lb = g_L + (size_t)bh * NN * NN;
    const float* Vb = g_V + (size_t)b * NN * CC + h * DD;

    float acc[7][7];
#pragma unroll
    for (int i = 0; i < 7; i++)
#pragma unroll
        for (int j = 0; j < 7; j++) acc[i][j] = 0.f;

    for (int m0 = 0; m0 < NN; m0 += 14) {
        for (int v = t; v < 1372; v += 196) {
            int r = v / 14, c = v - r * 14;
            As[c][r] = Lb[(size_t)(n0 + r) * NN + m0 + c];
        }
        for (int v = t; v < 1372; v += 196) {
            int kr = v / 98, mc = v - kr * 98;
            Bs[kr][mc] = Vb[(size_t)(m0 + kr) * CC + c0 + mc];
        }
        __syncthreads();
#pragma unroll
        for (int kk = 0; kk < 14; kk++) {
            float a[7], bb[7];
#pragma unroll
            for (int i = 0; i < 7; i++) a[i]  = As[kk][ty * 7 + i];
#pragma unroll
            for (int j = 0; j < 7; j++) bb[j] = Bs[kk][tx * 7 + j];
#pragma unroll
            for (int i = 0; i < 7; i++)
#pragma unroll
                for (int j = 0; j < 7; j++)
                    acc[i][j] = fmaf(a[i], bb[j], acc[i][j]);
        }
        __syncthreads();
    }

    __half* Oh = g_Oh + (size_t)b * NN * CC + h * DD;
#pragma unroll
    for (int i = 0; i < 7; i++)
#pragma unroll
        for (int j = 0; j < 7; j++)
            Oh[(size_t)(n0 + ty * 7 + i) * CC + c0 + tx * 7 + j] =
                __float2half_rn(acc[i][j]);
}

// ---------------- launcher --------------------------------------------------
extern "C" void kernel_launch(void* const* d_in, const int* in_sizes, int n_in,
                              void* d_out, int out_size)
{
    const float* x     = (const float*)d_in[0];
    const float* Wq    = (const float*)d_in[1];
    const float* bq    = (const float*)d_in[2];
    const float* Wk    = (const float*)d_in[3];
    const float* bk    = (const float*)d_in[4];
    const float* Wv    = (const float*)d_in[5];
    const float* bv    = (const float*)d_in[6];
    const float* Wo    = (const float*)d_in[7];
    const float* bo    = (const float*)d_in[8];
    const float* rel_h = (const float*)d_in[9];
    const float* rel_w = (const float*)d_in[10];
    float* out = (float*)d_out;

    float  *pQ, *pK, *pV;
    __half *pXh, *pXl, *pOh, *pWqh, *pWql, *pWkh, *pWvh, *pWoh;
    cudaGetSymbolAddress((void**)&pQ,   g_Q);
    cudaGetSymbolAddress((void**)&pK,   g_K);
    cudaGetSymbolAddress((void**)&pV,   g_V);
    cudaGetSymbolAddress((void**)&pXh,  g_Xh);
    cudaGetSymbolAddress((void**)&pXl,  g_Xl);
    cudaGetSymbolAddress((void**)&pOh,  g_Oh);
    cudaGetSymbolAddress((void**)&pWqh, g_Wqh);
    cudaGetSymbolAddress((void**)&pWql, g_Wql);
    cudaGetSymbolAddress((void**)&pWkh, g_Wkh);
    cudaGetSymbolAddress((void**)&pWvh, g_Wvh);
    cudaGetSymbolAddress((void**)&pWoh, g_Woh);

    const unsigned smem3 = NSTAGE * STG3 * sizeof(__half);  // 92160 B
    const unsigned smem1 = NSTAGE * STG1 * sizeof(__half);  // 46080 B
    cudaFuncSetAttribute(hgemm_proj3,
        cudaFuncAttributeMaxDynamicSharedMemorySize, smem3);
    cudaFuncSetAttribute(hgemm_proj1,
        cudaFuncAttributeMaxDynamicSharedMemorySize, smem1);

    const int xn = MM * CC;
    const int wn = CC * CC;
    f2h_split_kernel<<<(xn + 255) / 256, 256>>>(x,  pXh, pXl, xn);
    f2h_split_kernel<<<(wn + 255) / 256, 256>>>(Wq, pWqh, pWql, wn);
    f2h_hi_kernel<<<(wn + 255) / 256, 256>>>(Wk, pWkh, wn);
    f2h_hi_kernel<<<(wn + 255) / 256, 256>>>(Wv, pWvh, wn);
    f2h_hi_kernel<<<(wn + 255) / 256, 256>>>(Wo, pWoh, wn);

    cp_kernel<<<(HH * NN * DD + 255) / 256, 256>>>(rel_h, rel_w);

    dim3 pgrid(CC / 112, MM / 128);   // (7, 392)
    hgemm_proj3<<<pgrid, 256, smem3>>>(pXh, pXl, pWqh, pWql, bq, pQ);
    hgemm_proj1<<<pgrid, 256, smem1>>>(pXh, pWkh, bk, pK);
    hgemm_proj1<<<pgrid, 256, smem1>>>(pXh, pWvh, bv, pV);

    attn_logits_kernel<<<dim3(2, 2, BB * HH), 196>>>();
    softmax_kernel<<<BB * HH * NN / 8, 256>>>();
    attn_v_kernel<<<dim3(2, 2, BB * HH), 196>>>();

    hgemm_proj1<<<pgrid, 256, smem1>>>(pOh, pWoh, bo, out);
}

// round 7
// speedup vs baseline: 3.8811x; 1.6218x over previous
#include <cuda_runtime.h>
#include <cuda_fp16.h>
#include <math.h>

#define BB 256
#define NN 196
#define CC 784
#define HH 4
#define DD 196
#define MM (BB*NN)          // 50176 tokens
#define PSTR 216            // padded col stride (halves) for attn operands
#define PROWS 256           // padded rows per (b,h)
#define NBH (BB*HH)

// ---------------- scratch (device globals; pads rely on zero-init) ----------
__device__ __align__(16) float  g_L[(size_t)NBH * NN * NN];
__device__ __align__(16) __half g_Xh[(size_t)MM * CC];
__device__ __align__(16) __half g_Xl[(size_t)MM * CC];
__device__ __align__(16) __half g_Oh[(size_t)MM * CC];
__device__ __align__(16) __half g_Wqh[CC * CC];
__device__ __align__(16) __half g_Wql[CC * CC];
__device__ __align__(16) __half g_Wkh[CC * CC];
__device__ __align__(16) __half g_Wvh[CC * CC];
__device__ __align__(16) __half g_Woh[CC * CC];
// attention operands, padded [bh][PROWS][PSTR]; pads stay zero forever
__device__ __align__(16) __half g_qh [(size_t)NBH * PROWS * PSTR];
__device__ __align__(16) __half g_ql [(size_t)NBH * PROWS * PSTR];
__device__ __align__(16) __half g_qth[(size_t)NBH * PROWS * PSTR];
__device__ __align__(16) __half g_qtl[(size_t)NBH * PROWS * PSTR];
__device__ __align__(16) __half g_kh [(size_t)NBH * PROWS * PSTR];
__device__ __align__(16) __half g_vth[(size_t)NBH * PROWS * PSTR];
__device__ __align__(16) __half g_ph [(size_t)NBH * PROWS * PSTR];
__device__ __align__(16) __half g_cph[HH * PROWS * PSTR];
__device__ __align__(16) __half g_cpl[HH * PROWS * PSTR];

// ---------------- helpers ----------------------------------------------------
__device__ __forceinline__ void mma16816(float* c, const unsigned* a, const unsigned* b) {
    asm volatile("mma.sync.aligned.m16n8k16.row.col.f32.f16.f16.f32 "
                 "{%0,%1,%2,%3}, {%4,%5,%6,%7}, {%8,%9}, {%0,%1,%2,%3};"
                 : "+f"(c[0]), "+f"(c[1]), "+f"(c[2]), "+f"(c[3])
                 : "r"(a[0]), "r"(a[1]), "r"(a[2]), "r"(a[3]), "r"(b[0]), "r"(b[1]));
}
__device__ __forceinline__ void ldsm_x4(unsigned* d, const __half* p) {
    unsigned s = (unsigned)__cvta_generic_to_shared(p);
    asm volatile("ldmatrix.sync.aligned.m8n8.x4.shared.b16 {%0,%1,%2,%3}, [%4];"
                 : "=r"(d[0]), "=r"(d[1]), "=r"(d[2]), "=r"(d[3]) : "r"(s));
}
__device__ __forceinline__ void ldsm_x2(unsigned* d, const __half* p) {
    unsigned s = (unsigned)__cvta_generic_to_shared(p);
    asm volatile("ldmatrix.sync.aligned.m8n8.x2.shared.b16 {%0,%1}, [%2];"
                 : "=r"(d[0]), "=r"(d[1]) : "r"(s));
}
#define CPA16(s, g) asm volatile("cp.async.cg.shared.global [%0], [%1], 16;" \
    :: "r"((unsigned)__cvta_generic_to_shared(s)), "l"(g))
#define CPA_COMMIT() asm volatile("cp.async.commit_group;")
#define CPA_WAIT3()  asm volatile("cp.async.wait_group 3;")
#define CPA_WAIT0()  asm volatile("cp.async.wait_group 0;")

// ---------------- conversions ------------------------------------------------
__global__ void f2h_split_kernel(const float* __restrict__ in,
                                 __half* __restrict__ hi,
                                 __half* __restrict__ lo, int n) {
    int i = blockIdx.x * blockDim.x + threadIdx.x;
    if (i >= n) return;
    float f = in[i];
    __half h = __float2half_rn(f);
    hi[i] = h;
    lo[i] = __float2half_rn(f - __half2float(h));
}
__global__ void f2h_hi_kernel(const float* __restrict__ in,
                              __half* __restrict__ hi, int n) {
    int i = blockIdx.x * blockDim.x + threadIdx.x;
    if (i >= n) return;
    hi[i] = __float2half_rn(in[i]);
}

// cp[h][p][k] = rel_h[h,k,p/14] + rel_w[h,k,p%14], split hi/lo, padded
__global__ void cp_split_kernel(const float* __restrict__ rel_h,
                                const float* __restrict__ rel_w) {
    int idx = blockIdx.x * blockDim.x + threadIdx.x;
    if (idx >= HH * NN * DD) return;
    int h   = idx / (NN * DD);
    int rem = idx - h * (NN * DD);
    int p   = rem / DD;
    int k   = rem - p * DD;
    float v = rel_h[(h * DD + k) * 14 + (p / 14)]
            + rel_w[(h * DD + k) * 14 + (p % 14)];
    __half hi = __float2half_rn(v);
    size_t o = ((size_t)h * PROWS + p) * PSTR + k;
    g_cph[o] = hi;
    g_cpl[o] = __float2half_rn(v - __half2float(hi));
}

#define AST2 24
#define NSTAGE 4
#define KITERS 49

// ============ 3-term split-fp16 HMMA GEMM: Q projection ======================
#define STG3 ((128 + 128 + 112 + 112) * AST2)

__global__ __launch_bounds__(256) void hgemm_proj3(
    const __half* __restrict__ Ah, const __half* __restrict__ Al,
    const __half* __restrict__ Wh, const __half* __restrict__ Wl,
    const float* __restrict__ bias)
{
    extern __shared__ __half sm[];
    const int t    = threadIdx.x;
    const int lane = t & 31;
    const int wid  = t >> 5;
    const int wm   = wid & 3;
    const int wn   = wid >> 2;
    const int m0   = blockIdx.y * 128;
    const int n0   = blockIdx.x * 112;

    float acc[2][7][4];
#pragma unroll
    for (int i = 0; i < 2; i++)
#pragma unroll
        for (int j = 0; j < 7; j++)
#pragma unroll
            for (int r = 0; r < 4; r++) acc[i][j][r] = 0.f;

    auto prefetch = [&](int kt) {
        const int k0 = kt * 16;
        __half* st = sm + (kt & (NSTAGE - 1)) * STG3;
        for (int v = t; v < 960; v += 256) {
            const __half* g; __half* s;
            if (v < 512) {
                int part = v >> 8, rem = v & 255;
                int row = rem >> 1, ch = rem & 1;
                g = (part ? Al : Ah) + (size_t)(m0 + row) * CC + k0 + ch * 8;
                s = st + part * (128 * AST2) + row * AST2 + ch * 8;
            } else {
                int v2 = v - 512;
                int part = v2 / 224, rem = v2 % 224;
                int row = rem >> 1, ch = rem & 1;
                g = (part ? Wl : Wh) + (size_t)(n0 + row) * CC + k0 + ch * 8;
                s = st + 256 * AST2 + part * (112 * AST2) + row * AST2 + ch * 8;
            }
            CPA16(s, g);
        }
        CPA_COMMIT();
    };

    prefetch(0); prefetch(1); prefetch(2);

    for (int kt = 0; kt < KITERS; kt++) {
        if (kt + 3 < KITERS) prefetch(kt + 3);
        else CPA_COMMIT();
        CPA_WAIT3();
        __syncthreads();

        __half* st  = sm + (kt & (NSTAGE - 1)) * STG3;
        __half* Ash = st;
        __half* Asl = st + 128 * AST2;
        __half* Bsh = st + 256 * AST2;
        __half* Bsl = st + 256 * AST2 + 112 * AST2;

        unsigned afh[2][4], afl[2][4];
#pragma unroll
        for (int mt = 0; mt < 2; mt++) {
            int arow = wm * 32 + mt * 16 + (lane & 15);
            int acol = (lane >> 4) << 3;
            ldsm_x4(afh[mt], Ash + arow * AST2 + acol);
            ldsm_x4(afl[mt], Asl + arow * AST2 + acol);
        }
        unsigned bfh[7][2], bfl[7][2];
#pragma unroll
        for (int p = 0; p < 3; p++) {
            int brow = wn * 56 + p * 16 + (lane & 7) + ((lane & 16) >> 1);
            int bcol = lane & 8;
            ldsm_x4(&bfh[2 * p][0], Bsh + brow * AST2 + bcol);
            ldsm_x4(&bfl[2 * p][0], Bsl + brow * AST2 + bcol);
        }
        {
            int brow = wn * 56 + 48 + (lane & 7);
            int bcol = lane & 8;
            ldsm_x2(bfh[6], Bsh + brow * AST2 + bcol);
            ldsm_x2(bfl[6], Bsl + brow * AST2 + bcol);
        }
#pragma unroll
        for (int mt = 0; mt < 2; mt++)
#pragma unroll
            for (int nt = 0; nt < 7; nt++) {
                mma16816(acc[mt][nt], afh[mt], bfh[nt]);
                mma16816(acc[mt][nt], afh[mt], bfl[nt]);
                mma16816(acc[mt][nt], afl[mt], bfh[nt]);
            }
        __syncthreads();
    }

    // epilogue: split to hi/lo, write q + q^T padded attention layouts
    auto put = [&](int row, int col, float f) {
        int b = row / NN, n = row - b * NN;
        int h = col / DD, d = col - h * DD;
        size_t bh = (size_t)b * HH + h;
        size_t o1 = (bh * PROWS + n) * PSTR + d;
        size_t o2 = (bh * PROWS + d) * PSTR + n;
        __half hi = __float2half_rn(f);
        __half lo = __float2half_rn(f - __half2float(hi));
        g_qh[o1]  = hi; g_ql[o1]  = lo;
        g_qth[o2] = hi; g_qtl[o2] = lo;
    };
#pragma unroll
    for (int mt = 0; mt < 2; mt++)
#pragma unroll
        for (int nt = 0; nt < 7; nt++) {
            int row = m0 + wm * 32 + mt * 16 + (lane >> 2);
            int col = n0 + wn * 56 + nt * 8 + (lane & 3) * 2;
            float b0 = bias[col], b1 = bias[col + 1];
            put(row,     col,     acc[mt][nt][0] + b0);
            put(row,     col + 1, acc[mt][nt][1] + b1);
            put(row + 8, col,     acc[mt][nt][2] + b0);
            put(row + 8, col + 1, acc[mt][nt][3] + b1);
        }
}

// ============ 1-term fp16 HMMA GEMM: K / V / O projections ==================
// MODE 0: K -> g_kh[bh][n][d];  MODE 1: V -> g_vth[bh][d][n];  MODE 2: fp32 Y
#define STG1 ((128 + 112) * AST2)

template<int MODE>
__global__ __launch_bounds__(256) void hgemm_proj1(
    const __half* __restrict__ Ah, const __half* __restrict__ Wh,
    const float* __restrict__ bias, float* __restrict__ Y)
{
    extern __shared__ __half sm[];
    const int t    = threadIdx.x;
    const int lane = t & 31;
    const int wid  = t >> 5;
    const int wm   = wid & 3;
    const int wn   = wid >> 2;
    const int m0   = blockIdx.y * 128;
    const int n0   = blockIdx.x * 112;

    float acc[2][7][4];
#pragma unroll
    for (int i = 0; i < 2; i++)
#pragma unroll
        for (int j = 0; j < 7; j++)
#pragma unroll
            for (int r = 0; r < 4; r++) acc[i][j][r] = 0.f;

    auto prefetch = [&](int kt) {
        const int k0 = kt * 16;
        __half* st = sm + (kt & (NSTAGE - 1)) * STG1;
        for (int v = t; v < 480; v += 256) {
            const __half* g; __half* s;
            if (v < 256) {
                int row = v >> 1, ch = v & 1;
                g = Ah + (size_t)(m0 + row) * CC + k0 + ch * 8;
                s = st + row * AST2 + ch * 8;
            } else {
                int v2 = v - 256;
                int row = v2 >> 1, ch = v2 & 1;
                g = Wh + (size_t)(n0 + row) * CC + k0 + ch * 8;
                s = st + 128 * AST2 + row * AST2 + ch * 8;
            }
            CPA16(s, g);
        }
        CPA_COMMIT();
    };

    prefetch(0); prefetch(1); prefetch(2);

    for (int kt = 0; kt < KITERS; kt++) {
        if (kt + 3 < KITERS) prefetch(kt + 3);
        else CPA_COMMIT();
        CPA_WAIT3();
        __syncthreads();

        __half* st  = sm + (kt & (NSTAGE - 1)) * STG1;
        __half* Ash = st;
        __half* Bsh = st + 128 * AST2;

        unsigned afh[2][4];
#pragma unroll
        for (int mt = 0; mt < 2; mt++) {
            int arow = wm * 32 + mt * 16 + (lane & 15);
            int acol = (lane >> 4) << 3;
            ldsm_x4(afh[mt], Ash + arow * AST2 + acol);
        }
        unsigned bfh[7][2];
#pragma unroll
        for (int p = 0; p < 3; p++) {
            int brow = wn * 56 + p * 16 + (lane & 7) + ((lane & 16) >> 1);
            int bcol = lane & 8;
            ldsm_x4(&bfh[2 * p][0], Bsh + brow * AST2 + bcol);
        }
        {
            int brow = wn * 56 + 48 + (lane & 7);
            int bcol = lane & 8;
            ldsm_x2(bfh[6], Bsh + brow * AST2 + bcol);
        }
#pragma unroll
        for (int mt = 0; mt < 2; mt++)
#pragma unroll
            for (int nt = 0; nt < 7; nt++)
                mma16816(acc[mt][nt], afh[mt], bfh[nt]);
        __syncthreads();
    }

    auto put = [&](int row, int col, float f) {
        if (MODE == 2) return;   // unused
        int b = row / NN, n = row - b * NN;
        int h = col / DD, d = col - h * DD;
        size_t bh = (size_t)b * HH + h;
        __half hi = __float2half_rn(f);
        if (MODE == 0) g_kh [(bh * PROWS + n) * PSTR + d] = hi;
        else           g_vth[(bh * PROWS + d) * PSTR + n] = hi;
    };
#pragma unroll
    for (int mt = 0; mt < 2; mt++)
#pragma unroll
        for (int nt = 0; nt < 7; nt++) {
            int row = m0 + wm * 32 + mt * 16 + (lane >> 2);
            int col = n0 + wn * 56 + nt * 8 + (lane & 3) * 2;
            float b0 = bias[col], b1 = bias[col + 1];
            if (MODE == 2) {
                float2 v0 = make_float2(acc[mt][nt][0] + b0, acc[mt][nt][1] + b1);
                float2 v1 = make_float2(acc[mt][nt][2] + b0, acc[mt][nt][3] + b1);
                *(float2*)(Y + (size_t)row * CC + col) = v0;
                *(float2*)(Y + (size_t)(row + 8) * CC + col) = v1;
            } else {
                put(row,     col,     acc[mt][nt][0] + b0);
                put(row,     col + 1, acc[mt][nt][1] + b1);
                put(row + 8, col,     acc[mt][nt][2] + b0);
                put(row + 8, col + 1, acc[mt][nt][3] + b1);
            }
        }
}

// ============ HMMA logits: L = (Q@K^T)/14 + cp@Q ============================
// tile 112x112, 7 warps (224 thr), warp = 1 m16 x 14 n8. 13 k16 steps (pad 208).
#define TST (112 * AST2)            // 2688 halves per tile
#define LSTG (4 * TST)              // pass2 stage: 4 tiles

__global__ __launch_bounds__(224) void attn_logits_mma()
{
    extern __shared__ __half sm[];
    const int t    = threadIdx.x;
    const int lane = t & 31;
    const int wid  = t >> 5;        // 0..6
    const int bh   = blockIdx.z;
    const int h    = bh & (HH - 1);
    const int n0   = blockIdx.y * 112;
    const int m0   = blockIdx.x * 112;

    const __half* qh  = g_qh  + (size_t)bh * PROWS * PSTR;
    const __half* kh  = g_kh  + (size_t)bh * PROWS * PSTR;
    const __half* qth = g_qth + (size_t)bh * PROWS * PSTR;
    const __half* qtl = g_qtl + (size_t)bh * PROWS * PSTR;
    const __half* cph = g_cph + (size_t)h * PROWS * PSTR;
    const __half* cpl = g_cpl + (size_t)h * PROWS * PSTR;

    float acc[14][4];
#pragma unroll
    for (int j = 0; j < 14; j++)
#pragma unroll
        for (int r = 0; r < 4; r++) acc[j][r] = 0.f;

    // ---- pass 1: Q@K^T ----
    auto pf1 = [&](int kt) {
        const int k0 = kt * 16;
        __half* st = sm + (kt & 3) * LSTG;
        for (int v = t; v < 448; v += 224) {
            int tile = v >> 8, rem = v & 255;           // tile0:224..? careful
            // 448 = 2 tiles x 224; decode manually:
            tile = v / 224; rem = v - tile * 224;
            int row = rem >> 1, ch = rem & 1;
            const __half* g = (tile ? kh + (size_t)(m0 + row) * PSTR
                                    : qh + (size_t)(n0 + row) * PSTR) + k0 + ch * 8;
            CPA16(st + tile * TST + row * AST2 + ch * 8, g);
        }
        CPA_COMMIT();
    };
    pf1(0); pf1(1); pf1(2);
    for (int kt = 0; kt < 13; kt++) {
        if (kt + 3 < 13) pf1(kt + 3);
        else CPA_COMMIT();
        CPA_WAIT3();
        __syncthreads();
        __half* st = sm + (kt & 3) * LSTG;
        unsigned af[4];
        ldsm_x4(af, st + (wid * 16 + (lane & 15)) * AST2 + ((lane >> 4) << 3));
        unsigned bf[14][2];
#pragma unroll
        for (int p = 0; p < 7; p++) {
            int brow = p * 16 + (lane & 7) + ((lane & 16) >> 1);
            ldsm_x4(&bf[2 * p][0], st + TST + brow * AST2 + (lane & 8));
        }
#pragma unroll
        for (int nt = 0; nt < 14; nt++) mma16816(acc[nt], af, bf[nt]);
        __syncthreads();
    }
    CPA_WAIT0();
    __syncthreads();

#pragma unroll
    for (int j = 0; j < 14; j++)
#pragma unroll
        for (int r = 0; r < 4; r++) acc[j][r] *= (1.0f / 14.0f);

    // ---- pass 2: cp@Q, 3-term ----
    auto pf2 = [&](int kt) {
        const int k0 = kt * 16;
        __half* st = sm + (kt & 3) * LSTG;
        for (int v = t; v < 896; v += 224) {
            int tile = v / 224, rem = v - tile * 224;
            int row = rem >> 1, ch = rem & 1;
            const __half* g;
            if (tile == 0)      g = cph + (size_t)(n0 + row) * PSTR + k0 + ch * 8;
            else if (tile == 1) g = cpl + (size_t)(n0 + row) * PSTR + k0 + ch * 8;
            else if (tile == 2) g = qth + (size_t)(m0 + row) * PSTR + k0 + ch * 8;
            else                g = qtl + (size_t)(m0 + row) * PSTR + k0 + ch * 8;
            CPA16(st + tile * TST + row * AST2 + ch * 8, g);
        }
        CPA_COMMIT();
    };
    pf2(0); pf2(1); pf2(2);
    for (int kt = 0; kt < 13; kt++) {
        if (kt + 3 < 13) pf2(kt + 3);
        else CPA_COMMIT();
        CPA_WAIT3();
        __syncthreads();
        __half* st = sm + (kt & 3) * LSTG;
        unsigned afh[4], afl[4];
        int arow = wid * 16 + (lane & 15);
        int acol = (lane >> 4) << 3;
        ldsm_x4(afh, st + arow * AST2 + acol);
        ldsm_x4(afl, st + TST + arow * AST2 + acol);
        unsigned bfh[14][2], bfl[14][2];
#pragma unroll
        for (int p = 0; p < 7; p++) {
            int brow = p * 16 + (lane & 7) + ((lane & 16) >> 1);
            ldsm_x4(&bfh[2 * p][0], st + 2 * TST + brow * AST2 + (lane & 8));
            ldsm_x4(&bfl[2 * p][0], st + 3 * TST + brow * AST2 + (lane & 8));
        }
#pragma unroll
        for (int nt = 0; nt < 14; nt++) {
            mma16816(acc[nt], afh, bfh[nt]);
            mma16816(acc[nt], afl, bfh[nt]);
            mma16816(acc[nt], afh, bfl[nt]);
        }
        __syncthreads();
    }

    // epilogue -> fp32 logits, bounds-checked
    float* Lb = g_L + (size_t)bh * NN * NN;
#pragma unroll
    for (int nt = 0; nt < 14; nt++) {
        int row = n0 + wid * 16 + (lane >> 2);
        int col = m0 + nt * 8 + (lane & 3) * 2;
        if (col < NN) {
            if (row < NN)
                *(float2*)(Lb + (size_t)row * NN + col) =
                    make_float2(acc[nt][0], acc[nt][1]);
            if (row + 8 < NN)
                *(float2*)(Lb + (size_t)(row + 8) * NN + col) =
                    make_float2(acc[nt][2], acc[nt][3]);
        }
    }
}

// ---------------- softmax: fp32 L -> fp16 P (padded layout) -----------------
__global__ __launch_bounds__(256) void softmax_kernel()
{
    const int warp = threadIdx.x >> 5, lane = threadIdx.x & 31;
    const size_t row = (size_t)blockIdx.x * 8 + warp;   // over NBH*NN rows
    const float* p = g_L + row * NN;
    const int bh = (int)(row / NN), n = (int)(row - (size_t)bh * NN);
    __half* po = g_ph + ((size_t)bh * PROWS + n) * PSTR;

    float v[7];
    float mx = -1e30f;
#pragma unroll
    for (int s = 0; s < 7; s++) {
        int idx = lane + s * 32;
        v[s] = (idx < NN) ? p[idx] : -1e30f;
        mx = fmaxf(mx, v[s]);
    }
#pragma unroll
    for (int o = 16; o; o >>= 1) mx = fmaxf(mx, __shfl_xor_sync(0xffffffffu, mx, o));
    float sum = 0.f;
#pragma unroll
    for (int s = 0; s < 7; s++) { v[s] = __expf(v[s] - mx); sum += v[s]; }
#pragma unroll
    for (int o = 16; o; o >>= 1) sum += __shfl_xor_sync(0xffffffffu, sum, o);
    float inv = 1.0f / sum;
#pragma unroll
    for (int s = 0; s < 7; s++) {
        int idx = lane + s * 32;
        if (idx < NN) po[idx] = __float2half_rn(v[s] * inv);
    }
}

// ============ HMMA P@V -> fp16 O (B,N,C) ====================================
#define VSTG (2 * TST)

__global__ __launch_bounds__(224) void attn_pv_mma()
{
    extern __shared__ __half sm[];
    const int t    = threadIdx.x;
    const int lane = t & 31;
    const int wid  = t >> 5;
    const int bh   = blockIdx.z;
    const int b    = bh >> 2, h = bh & 3;
    const int n0   = blockIdx.y * 112;
    const int c0   = blockIdx.x * 112;

    const __half* ph  = g_ph  + (size_t)bh * PROWS * PSTR;
    const __half* vth = g_vth + (size_t)bh * PROWS * PSTR;

    float acc[14][4];
#pragma unroll
    for (int j = 0; j < 14; j++)
#pragma unroll
        for (int r = 0; r < 4; r++) acc[j][r] = 0.f;

    auto pf = [&](int kt) {
        const int k0 = kt * 16;
        __half* st = sm + (kt & 3) * VSTG;
        for (int v = t; v < 448; v += 224) {
            int tile = v / 224, rem = v - tile * 224;
            int row = rem >> 1, ch = rem & 1;
            const __half* g = (tile ? vth + (size_t)(c0 + row) * PSTR
                                    : ph + (size_t)(n0 + row) * PSTR) + k0 + ch * 8;
            CPA16(st + tile * TST + row * AST2 + ch * 8, g);
        }
        CPA_COMMIT();
    };
    pf(0); pf(1); pf(2);
    for (int kt = 0; kt < 13; kt++) {
        if (kt + 3 < 13) pf(kt + 3);
        else CPA_COMMIT();
        CPA_WAIT3();
        __syncthreads();
        __half* st = sm + (kt & 3) * VSTG;
        unsigned af[4];
        ldsm_x4(af, st + (wid * 16 + (lane & 15)) * AST2 + ((lane >> 4) << 3));
        unsigned bf[14][2];
#pragma unroll
        for (int p = 0; p < 7; p++) {
            int brow = p * 16 + (lane & 7) + ((lane & 16) >> 1);
            ldsm_x4(&bf[2 * p][0], st + TST + brow * AST2 + (lane & 8));
        }
#pragma unroll
        for (int nt = 0; nt < 14; nt++) mma16816(acc[nt], af, bf[nt]);
        __syncthreads();
    }

    // epilogue -> g_Oh[(b*196+n)][h*196+c], fp16
#pragma unroll
    for (int nt = 0; nt < 14; nt++) {
        int n = n0 + wid * 16 + (lane >> 2);
        int c = c0 + nt * 8 + (lane & 3) * 2;
        if (c < NN) {
            size_t colo = (size_t)h * DD + c;
            if (n < NN) {
                size_t ro = ((size_t)b * NN + n) * CC + colo;
                g_Oh[ro]     = __float2half_rn(acc[nt][0]);
                g_Oh[ro + 1] = __float2half_rn(acc[nt][1]);
            }
            if (n + 8 < NN) {
                size_t ro = ((size_t)b * NN + n + 8) * CC + colo;
                g_Oh[ro]     = __float2half_rn(acc[nt][2]);
                g_Oh[ro + 1] = __float2half_rn(acc[nt][3]);
            }
        }
    }
}

// ---------------- launcher --------------------------------------------------
extern "C" void kernel_launch(void* const* d_in, const int* in_sizes, int n_in,
                              void* d_out, int out_size)
{
    const float* x     = (const float*)d_in[0];
    const float* Wq    = (const float*)d_in[1];
    const float* bq    = (const float*)d_in[2];
    const float* Wk    = (const float*)d_in[3];
    const float* bk    = (const float*)d_in[4];
    const float* Wv    = (const float*)d_in[5];
    const float* bv    = (const float*)d_in[6];
    const float* Wo    = (const float*)d_in[7];
    const float* bo    = (const float*)d_in[8];
    const float* rel_h = (const float*)d_in[9];
    const float* rel_w = (const float*)d_in[10];
    float* out = (float*)d_out;

    __half *pXh, *pXl, *pOh, *pWqh, *pWql, *pWkh, *pWvh, *pWoh;
    cudaGetSymbolAddress((void**)&pXh,  g_Xh);
    cudaGetSymbolAddress((void**)&pXl,  g_Xl);
    cudaGetSymbolAddress((void**)&pOh,  g_Oh);
    cudaGetSymbolAddress((void**)&pWqh, g_Wqh);
    cudaGetSymbolAddress((void**)&pWql, g_Wql);
    cudaGetSymbolAddress((void**)&pWkh, g_Wkh);
    cudaGetSymbolAddress((void**)&pWvh, g_Wvh);
    cudaGetSymbolAddress((void**)&pWoh, g_Woh);

    const unsigned smem3 = NSTAGE * STG3 * sizeof(__half);   // 92160
    const unsigned smem1 = NSTAGE * STG1 * sizeof(__half);   // 46080
    const unsigned smemL = 4 * LSTG * sizeof(__half);        // 86016
    const unsigned smemV = 4 * VSTG * sizeof(__half);        // 43008
    cudaFuncSetAttribute(hgemm_proj3,
        cudaFuncAttributeMaxDynamicSharedMemorySize, smem3);
    cudaFuncSetAttribute(hgemm_proj1<0>,
        cudaFuncAttributeMaxDynamicSharedMemorySize, smem1);
    cudaFuncSetAttribute(hgemm_proj1<1>,
        cudaFuncAttributeMaxDynamicSharedMemorySize, smem1);
    cudaFuncSetAttribute(hgemm_proj1<2>,
        cudaFuncAttributeMaxDynamicSharedMemorySize, smem1);
    cudaFuncSetAttribute(attn_logits_mma,
        cudaFuncAttributeMaxDynamicSharedMemorySize, smemL);
    cudaFuncSetAttribute(attn_pv_mma,
        cudaFuncAttributeMaxDynamicSharedMemorySize, smemV);

    const int xn = MM * CC;
    const int wn = CC * CC;
    f2h_split_kernel<<<(xn + 255) / 256, 256>>>(x,  pXh, pXl, xn);
    f2h_split_kernel<<<(wn + 255) / 256, 256>>>(Wq, pWqh, pWql, wn);
    f2h_hi_kernel<<<(wn + 255) / 256, 256>>>(Wk, pWkh, wn);
    f2h_hi_kernel<<<(wn + 255) / 256, 256>>>(Wv, pWvh, wn);
    f2h_hi_kernel<<<(wn + 255) / 256, 256>>>(Wo, pWoh, wn);
    cp_split_kernel<<<(HH * NN * DD + 255) / 256, 256>>>(rel_h, rel_w);

    dim3 pgrid(CC / 112, MM / 128);   // (7, 392)
    hgemm_proj3<<<pgrid, 256, smem3>>>(pXh, pXl, pWqh, pWql, bq);
    hgemm_proj1<0><<<pgrid, 256, smem1>>>(pXh, pWkh, bk, nullptr);
    hgemm_proj1<1><<<pgrid, 256, smem1>>>(pXh, pWvh, bv, nullptr);

    attn_logits_mma<<<dim3(2, 2, NBH), 224, smemL>>>();
    softmax_kernel<<<NBH * NN / 8, 256>>>();
    attn_pv_mma<<<dim3(2, 2, NBH), 224, smemV>>>();

    hgemm_proj1<2><<<pgrid, 256, smem1>>>(pOh, pWoh, bo, out);
}